// round 15
// baseline (speedup 1.0000x reference)
#include <cuda_runtime.h>
#include <cuda_bf16.h>
#include <cstddef>
#include <cstdint>
#include <math.h>

// ---------------- problem constants ----------------
#define Lc   4
#define Hc   2048
#define NHc  16
#define NKVc 4
#define DHc  128
#define Fc   5632
#define Rc   16
#define Bc   4
#define Sc   512
#define NCc  2
#define MTc  (Bc * Sc)
#define QNc  (NHc * DHc)        // 2048
#define KNc  (NKVc * DHc)       // 512
#define LORA_SCALE 2.0f
#define INV_SQRT_DH 0.08838834764831845f

// per-layer transposed weight buffer offsets (elements) — [N,K] packing
#define WOFF_Q 0
#define WOFF_K (WOFF_Q + Hc * QNc)
#define WOFF_V (WOFF_K + Hc * KNc)
#define WOFF_O (WOFF_V + Hc * KNc)
#define WOFF_G (WOFF_O + QNc * Hc)
#define WOFF_U (WOFF_G + Hc * Fc)
#define WOFF_D (WOFF_U + Hc * Fc)
#define LAYER_W (WOFF_D + Fc * Hc)   // 45,088,768
// weight row offsets within a layer (rows of W^T)
#define ROFF_Q 0
#define ROFF_K 2048
#define ROFF_V 2560
#define ROFF_O 3072
#define ROFF_G 5120
#define ROFF_U 10752
#define ROFF_D 16384
#define ROWS_PER_LAYER 18432

// ---------------- scratch (static device memory; allocation-free) ----------------
__device__ float          d_h[MTc * Hc];
__device__ int8_t         d_x8h[MTc * Hc];
__device__ int8_t         d_x8l[MTc * Hc];
__device__ float          d_xinv[MTc];
__device__ float          d_q[MTc * QNc];
__device__ float          d_k[MTc * KNc];
__device__ float          d_v[MTc * KNc];
__device__ __nv_bfloat16  d_qh[MTc * QNc];
__device__ __nv_bfloat16  d_ql[MTc * QNc];
__device__ __nv_bfloat16  d_kh[MTc * KNc];
__device__ __nv_bfloat16  d_kl[MTc * KNc];
__device__ __nv_bfloat16  d_vTh[Bc * KNc * Sc];
__device__ __nv_bfloat16  d_vTl[Bc * KNc * Sc];
__device__ float          d_ropec[Sc * 64];
__device__ float          d_ropes[Sc * 64];
__device__ float          d_sc[Bc * NHc * Sc * Sc];
__device__ __nv_bfloat16  d_ph[Bc * NHc * Sc * Sc];
__device__ __nv_bfloat16  d_pl[Bc * NHc * Sc * Sc];
__device__ float          d_ctx[MTc * QNc];
__device__ int8_t         d_c8h[MTc * QNc];
__device__ int8_t         d_c8l[MTc * QNc];
__device__ float          d_cinv[MTc];
__device__ float          d_g[MTc * Fc];
__device__ float          d_u[MTc * Fc];
__device__ int8_t         d_g8h[MTc * Fc];
__device__ int8_t         d_g8l[MTc * Fc];
__device__ float          d_ginv[MTc];
__device__ float          d_pooled[Bc * Hc];
__device__ float          d_cls[Bc * Hc];
__device__ float          d_wt[(size_t)Lc * LAYER_W];    // fp32 folded W^T scratch
__device__ int8_t         d_w8h[(size_t)Lc * LAYER_W];
__device__ int8_t         d_w8l[(size_t)Lc * LAYER_W];
__device__ float          d_winv[Lc * ROWS_PER_LAYER];

// ---------------- PTX helpers ----------------
__device__ __forceinline__ uint32_t sptr(const void* p) {
    return (uint32_t)__cvta_generic_to_shared(p);
}
#define CP_ASYNC16(dst, src) asm volatile("cp.async.cg.shared.global [%0], [%1], 16;\n" :: "r"(dst), "l"(src))
#define CP_COMMIT()          asm volatile("cp.async.commit_group;\n" ::: "memory")
#define CP_WAIT(n)           asm volatile("cp.async.wait_group %0;\n" :: "n"(n) : "memory")

__device__ __forceinline__ void mma_bf16(float* c, const uint32_t* a, const uint32_t* b) {
    asm volatile(
        "mma.sync.aligned.m16n8k16.row.col.f32.bf16.bf16.f32 "
        "{%0,%1,%2,%3}, {%4,%5,%6,%7}, {%8,%9}, {%0,%1,%2,%3};\n"
        : "+f"(c[0]), "+f"(c[1]), "+f"(c[2]), "+f"(c[3])
        : "r"(a[0]), "r"(a[1]), "r"(a[2]), "r"(a[3]), "r"(b[0]), "r"(b[1]));
}

__device__ __forceinline__ void mma_s8(int* c, const uint32_t* a, const uint32_t* b) {
    asm volatile(
        "mma.sync.aligned.m16n8k32.row.col.s32.s8.s8.s32 "
        "{%0,%1,%2,%3}, {%4,%5,%6,%7}, {%8,%9}, {%0,%1,%2,%3};\n"
        : "+r"(c[0]), "+r"(c[1]), "+r"(c[2]), "+r"(c[3])
        : "r"(a[0]), "r"(a[1]), "r"(a[2]), "r"(a[3]), "r"(b[0]), "r"(b[1]));
}

__device__ __forceinline__ void ldsm4(uint32_t* r, uint32_t addr) {
    asm volatile("ldmatrix.sync.aligned.m8n8.x4.shared.b16 {%0,%1,%2,%3}, [%4];"
        : "=r"(r[0]), "=r"(r[1]), "=r"(r[2]), "=r"(r[3]) : "r"(addr));
}

// ---------------- weight fold+transpose -> fp32 scratch ----------------
#define TILES_PER_LAYER 22016
__global__ void wfoldT_kernel(const float* __restrict__ wq, const float* __restrict__ wk,
                              const float* __restrict__ wv, const float* __restrict__ wo,
                              const float* __restrict__ wg, const float* __restrict__ wu,
                              const float* __restrict__ wd,
                              const float* __restrict__ laq, const float* __restrict__ lbq,
                              const float* __restrict__ lak, const float* __restrict__ lbk,
                              const float* __restrict__ lav, const float* __restrict__ lbv,
                              const float* __restrict__ lao, const float* __restrict__ lbo,
                              float* __restrict__ wt) {
    int l = blockIdx.x / TILES_PER_LAYER;
    int r = blockIdx.x % TILES_PER_LAYER;
    const float* src; size_t woff; int K, N, tidx;
    const float* loA = nullptr; const float* loB = nullptr;
    if (r < 2048)       { src = wq + (size_t)l * Hc * QNc; woff = WOFF_Q; K = Hc;  N = QNc; tidx = r;
                          loA = laq + (size_t)l * Rc * Hc;  loB = lbq + (size_t)l * QNc * Rc; }
    else if (r < 2560)  { src = wk + (size_t)l * Hc * KNc; woff = WOFF_K; K = Hc;  N = KNc; tidx = r - 2048;
                          loA = lak + (size_t)l * Rc * Hc;  loB = lbk + (size_t)l * KNc * Rc; }
    else if (r < 3072)  { src = wv + (size_t)l * Hc * KNc; woff = WOFF_V; K = Hc;  N = KNc; tidx = r - 2560;
                          loA = lav + (size_t)l * Rc * Hc;  loB = lbv + (size_t)l * KNc * Rc; }
    else if (r < 5120)  { src = wo + (size_t)l * QNc * Hc; woff = WOFF_O; K = QNc; N = Hc;  tidx = r - 3072;
                          loA = lao + (size_t)l * Rc * QNc; loB = lbo + (size_t)l * Hc * Rc; }
    else if (r < 10752) { src = wg + (size_t)l * Hc * Fc;  woff = WOFF_G; K = Hc;  N = Fc;  tidx = r - 5120; }
    else if (r < 16384) { src = wu + (size_t)l * Hc * Fc;  woff = WOFF_U; K = Hc;  N = Fc;  tidx = r - 10752; }
    else                { src = wd + (size_t)l * Fc * Hc;  woff = WOFF_D; K = Fc;  N = Hc;  tidx = r - 16384; }
    woff += (size_t)l * LAYER_W;
    int nt = N / 32;
    int k0 = (tidx / nt) * 64, n0 = (tidx % nt) * 32;

    __shared__ float tile[64][33];
    __shared__ float sA[16][64];
    __shared__ float sB[32][17];
    int tx = threadIdx.x, ty = threadIdx.y;
    int tid = ty * 32 + tx;
    for (int i = ty; i < 64; i += 8)
        tile[i][tx] = src[(size_t)(k0 + i) * N + n0 + tx];
    if (loA) {
        for (int idx = tid; idx < 1024; idx += 256) {
            int rr = idx >> 6, kk = idx & 63;
            sA[rr][kk] = loA[(size_t)rr * K + k0 + kk];
        }
        for (int idx = tid; idx < 512; idx += 256) {
            int nn = idx >> 4, rr = idx & 15;
            sB[nn][rr] = loB[(size_t)(n0 + nn) * Rc + rr];
        }
    }
    __syncthreads();
    for (int i = ty; i < 32; i += 8) {
        float v0 = tile[2 * tx][i], v1 = tile[2 * tx + 1][i];
        if (loA) {
            float d0 = 0.f, d1 = 0.f;
            #pragma unroll
            for (int rr = 0; rr < Rc; rr++) {
                float bb = sB[i][rr];
                d0 += sA[rr][2 * tx] * bb;
                d1 += sA[rr][2 * tx + 1] * bb;
            }
            v0 += LORA_SCALE * d0;
            v1 += LORA_SCALE * d1;
        }
        size_t idx = woff + (size_t)(n0 + i) * K + k0 + 2 * tx;
        *(float2*)(wt + idx) = make_float2(v0, v1);
    }
}

// ---------------- per weight-row max -> binv = rowmax/127 ----------------
__global__ void wmax_kernel(const float* __restrict__ wt, float* __restrict__ winv) {
    int gid = blockIdx.x;
    int l = gid / ROWS_PER_LAYER;
    int r = gid % ROWS_PER_LAYER;
    int K = (r < ROFF_D) ? 2048 : Fc;
    size_t start = (size_t)l * LAYER_W +
                   ((r < ROFF_D) ? (size_t)r * 2048
                                 : (size_t)WOFF_D + (size_t)(r - ROFF_D) * Fc);
    const float* p = wt + start;
    float mx = 0.f;
    for (int i = threadIdx.x; i < K; i += 256) mx = fmaxf(mx, fabsf(p[i]));
    __shared__ float sh[256];
    sh[threadIdx.x] = mx; __syncthreads();
    for (int o = 128; o; o >>= 1) { if (threadIdx.x < o) sh[threadIdx.x] = fmaxf(sh[threadIdx.x], sh[threadIdx.x + o]); __syncthreads(); }
    if (threadIdx.x == 0) winv[gid] = fmaxf(sh[0], 1e-20f) * (1.0f / 127.0f);
}

// ---------------- weight quantize -> int8 hi/lo ----------------
__global__ void wquant_kernel(const float* __restrict__ wt, const float* __restrict__ winv,
                              int8_t* __restrict__ w8h, int8_t* __restrict__ w8l) {
    size_t idx4 = (size_t)blockIdx.x * 256 + threadIdx.x;
    size_t total4 = (size_t)Lc * LAYER_W / 4;
    if (idx4 >= total4) return;
    size_t off = idx4 * 4;
    int l = (int)(off / LAYER_W);
    size_t loff = off - (size_t)l * LAYER_W;
    int row = (loff < (size_t)WOFF_D) ? (int)(loff >> 11)
                                      : ROFF_D + (int)((loff - WOFF_D) / Fc);
    float qs = 1.0f / winv[l * ROWS_PER_LAYER + row];
    float4 v = *(const float4*)(wt + off);
    char4 hq, lq;
    {
        float xs = v.x * qs; int h = __float2int_rn(xs); int lo = __float2int_rn((xs - h) * 128.f);
        hq.x = (char)h; lq.x = (char)lo;
    }
    {
        float xs = v.y * qs; int h = __float2int_rn(xs); int lo = __float2int_rn((xs - h) * 128.f);
        hq.y = (char)h; lq.y = (char)lo;
    }
    {
        float xs = v.z * qs; int h = __float2int_rn(xs); int lo = __float2int_rn((xs - h) * 128.f);
        hq.z = (char)h; lq.z = (char)lo;
    }
    {
        float xs = v.w * qs; int h = __float2int_rn(xs); int lo = __float2int_rn((xs - h) * 128.f);
        hq.w = (char)h; lq.w = (char)lo;
    }
    *(char4*)(w8h + off) = hq;
    *(char4*)(w8l + off) = lq;
}

// ---------------- RoPE table precompute ----------------
__global__ void rope_table_kernel(float* __restrict__ rc, float* __restrict__ rs) {
    int s = blockIdx.x;
    int d = threadIdx.x;
    float freq = powf(1000000.0f, -(float)d / 64.0f);
    float ang = (float)s * freq;
    float sn, cs;
    sincosf(ang, &sn, &cs);
    rc[s * 64 + d] = cs;
    rs[s * 64 + d] = sn;
}

// ---------------- embedding gather ----------------
__global__ void embed_kernel(const int* __restrict__ ids,
                             const float* __restrict__ emb,
                             float* __restrict__ h) {
    int row = blockIdx.x;
    const float* src = emb + (size_t)ids[row] * Hc;
    float* dst = h + (size_t)row * Hc;
    for (int i = threadIdx.x; i < Hc; i += 256) dst[i] = src[i];
}

// ---------------- rmsnorm + int8 row quantize ----------------
__global__ void rmsnorm_q8(const float* __restrict__ in, const float* __restrict__ w,
                           int8_t* __restrict__ q8h, int8_t* __restrict__ q8l,
                           float* __restrict__ ainv) {
    int row = blockIdx.x;
    int t = threadIdx.x;
    const float* x = in + (size_t)row * Hc;
    float vbuf[8];
    float ss = 0.f;
    #pragma unroll
    for (int j = 0; j < 8; j++) { float v = x[t + 256 * j]; vbuf[j] = v; ss += v * v; }
    __shared__ float sh[256];
    sh[t] = ss; __syncthreads();
    for (int o = 128; o; o >>= 1) { if (t < o) sh[t] += sh[t + o]; __syncthreads(); }
    float sc = rsqrtf(sh[0] / (float)Hc + 1e-6f);
    __syncthreads();
    float mx = 0.f;
    #pragma unroll
    for (int j = 0; j < 8; j++) {
        vbuf[j] = vbuf[j] * sc * w[t + 256 * j];
        mx = fmaxf(mx, fabsf(vbuf[j]));
    }
    sh[t] = mx; __syncthreads();
    for (int o = 128; o; o >>= 1) { if (t < o) sh[t] = fmaxf(sh[t], sh[t + o]); __syncthreads(); }
    float rowmax = fmaxf(sh[0], 1e-20f);
    if (t == 0) ainv[row] = rowmax * (1.0f / 127.0f);
    float qs = 127.0f / rowmax;
    #pragma unroll
    for (int j = 0; j < 8; j++) {
        float xs = vbuf[j] * qs;
        int h = __float2int_rn(xs);
        int lo = __float2int_rn((xs - h) * 128.f);
        q8h[(size_t)row * Hc + t + 256 * j] = (int8_t)h;
        q8l[(size_t)row * Hc + t + 256 * j] = (int8_t)lo;
    }
}

// ---------------- generic fp32 row quantize -> int8 hi/lo ----------------
__global__ void quant8_rows(const float* __restrict__ src, int N,
                            int8_t* __restrict__ q8h, int8_t* __restrict__ q8l,
                            float* __restrict__ ainv) {
    int row = blockIdx.x;
    int t = threadIdx.x;
    const float* p = src + (size_t)row * N;
    float mx = 0.f;
    for (int i = t; i < N; i += 256) mx = fmaxf(mx, fabsf(p[i]));
    __shared__ float sh[256];
    sh[t] = mx; __syncthreads();
    for (int o = 128; o; o >>= 1) { if (t < o) sh[t] = fmaxf(sh[t], sh[t + o]); __syncthreads(); }
    float rowmax = fmaxf(sh[0], 1e-20f);
    if (t == 0) ainv[row] = rowmax * (1.0f / 127.0f);
    float qs = 127.0f / rowmax;
    for (int i = t; i < N; i += 256) {
        float xs = p[i] * qs;
        int h = __float2int_rn(xs);
        int lo = __float2int_rn((xs - h) * 128.f);
        q8h[(size_t)row * N + i] = (int8_t)h;
        q8l[(size_t)row * N + i] = (int8_t)lo;
    }
}

// ================= int8x3 GEMM: CTA 128x64, warp 32x32, K-stage 64 =================
#define OFF_AL 8192
#define OFF_BH 16384
#define OFF_BL 20480
#define STAGE_B 24576
#define NSTAGE 3
#define GEMM_SMEM (NSTAGE * STAGE_B)

struct I8Ctx {
    const int8_t *pAh, *pAl, *pBh, *pBl;
    uint32_t sb, srowA, srowB;
    int lgA, swA, gB, swB;
    int m0, n0, lrow16, lch, lsw;
};

__device__ __forceinline__ void i8_setup(I8Ctx& cx, uint8_t* smraw, int tid,
                                         const int8_t* Ahi, const int8_t* Alo,
                                         const int8_t* Bhi, const int8_t* Blo,
                                         int bm, int bn, int ldA, int ldB) {
    const int warpId = tid >> 5, lane = tid & 31;
    cx.m0 = (warpId & 3) * 32;
    cx.n0 = (warpId >> 2) * 32;
    cx.lrow16 = lane & 15;
    cx.lch = lane >> 4;
    cx.lsw = (cx.lrow16 >> 1) & 3;
    cx.sb = sptr(smraw);
    int lrowA = tid >> 1;
    cx.lgA = (tid & 1) * 2;
    cx.swA = (lrowA >> 1) & 3;
    cx.pAh = Ahi + (size_t)(bm + lrowA) * ldA;
    cx.pAl = Alo + (size_t)(bm + lrowA) * ldA;
    cx.srowA = cx.sb + lrowA * 64;
    int lrowB = tid >> 2;
    cx.gB = tid & 3;
    cx.swB = (lrowB >> 1) & 3;
    cx.pBh = Bhi + (size_t)(bn + lrowB) * ldB;
    cx.pBl = Blo + (size_t)(bn + lrowB) * ldB;
    cx.srowB = cx.sb + lrowB * 64;
}

__device__ __forceinline__ void i8_mainloop(I8Ctx& cx, int accS1[2][4][4], int accS2[2][4][4], int K) {
    auto loadStage = [&](int st, int k0) {
        uint32_t dA = cx.srowA + st * STAGE_B;
        #pragma unroll
        for (int i = 0; i < 2; i++) {
            int g = cx.lgA + i;
            uint32_t off = (uint32_t)(g ^ cx.swA) << 4;
            CP_ASYNC16(dA + off, cx.pAh + k0 + g * 16);
            CP_ASYNC16(dA + OFF_AL + off, cx.pAl + k0 + g * 16);
        }
        uint32_t dB = cx.srowB + st * STAGE_B;
        uint32_t offb = (uint32_t)(cx.gB ^ cx.swB) << 4;
        CP_ASYNC16(dB + OFF_BH + offb, cx.pBh + k0 + cx.gB * 16);
        CP_ASYNC16(dB + OFF_BL + offb, cx.pBl + k0 + cx.gB * 16);
        CP_COMMIT();
    };
    const int KT = K >> 6;
    loadStage(0, 0);
    if (KT > 1) loadStage(1, 64);

    for (int kt = 0; kt < KT; kt++) {
        const int st = kt % NSTAGE;
        if (kt + 1 < KT) { CP_WAIT(1); } else { CP_WAIT(0); }
        __syncthreads();
        if (kt + 2 < KT) loadStage((kt + 2) % NSTAGE, (kt + 2) << 6);

        const uint32_t tAh = cx.sb + st * STAGE_B;
        const uint32_t tAl = tAh + OFF_AL;
        const uint32_t tBh = tAh + OFF_BH;
        const uint32_t tBl = tAh + OFF_BL;

        #pragma unroll
        for (int ks = 0; ks < 2; ks++) {
            const uint32_t choff = (uint32_t)(((ks * 2 + cx.lch) ^ cx.lsw)) << 4;
            uint32_t ra0 = (uint32_t)(cx.m0 + cx.lrow16) * 64 + choff;
            uint32_t ra1 = (uint32_t)(cx.m0 + 16 + cx.lrow16) * 64 + choff;
            uint32_t rb0 = (uint32_t)(cx.n0 + cx.lrow16) * 64 + choff;

            uint32_t afH[2][4], afL[2][4], bf[4][2];
            #pragma unroll
            for (int np = 0; np < 2; np++) {
                uint32_t q[4];
                ldsm4(q, tBh + rb0 + (uint32_t)(np * 16 * 64));
                bf[2 * np][0] = q[0]; bf[2 * np + 1][0] = q[1];
                bf[2 * np][1] = q[2]; bf[2 * np + 1][1] = q[3];
            }
            ldsm4(afH[0], tAh + ra0);
            ldsm4(afH[1], tAh + ra1);
            #pragma unroll
            for (int mt = 0; mt < 2; mt++)
                #pragma unroll
                for (int nt = 0; nt < 4; nt++)
                    mma_s8(accS1[mt][nt], afH[mt], bf[nt]);
            ldsm4(afL[0], tAl + ra0);
            ldsm4(afL[1], tAl + ra1);
            #pragma unroll
            for (int mt = 0; mt < 2; mt++)
                #pragma unroll
                for (int nt = 0; nt < 4; nt++)
                    mma_s8(accS2[mt][nt], afL[mt], bf[nt]);
            #pragma unroll
            for (int np = 0; np < 2; np++) {
                uint32_t q[4];
                ldsm4(q, tBl + rb0 + (uint32_t)(np * 16 * 64));
                bf[2 * np][0] = q[0]; bf[2 * np + 1][0] = q[1];
                bf[2 * np][1] = q[2]; bf[2 * np + 1][1] = q[3];
            }
            #pragma unroll
            for (int mt = 0; mt < 2; mt++)
                #pragma unroll
                for (int nt = 0; nt < 4; nt++)
                    mma_s8(accS2[mt][nt], afH[mt], bf[nt]);
        }
    }
}

// ---------------- fused QKV int8 GEMM ----------------
__global__ __launch_bounds__(256, 2) void gemm_qkv_i8(
    const int8_t* __restrict__ Ahi, const int8_t* __restrict__ Alo,
    const float* __restrict__ ainv,
    const int8_t* __restrict__ w8h, const int8_t* __restrict__ w8l,
    const float* __restrict__ winvL,
    const float* __restrict__ BQ, const float* __restrict__ BK, const float* __restrict__ BV,
    float* __restrict__ q, float* __restrict__ k, float* __restrict__ v) {
    extern __shared__ uint8_t smraw[];
    const int tid = threadIdx.x;
    const int bx = blockIdx.x;
    const int bm = blockIdx.y * 128;

    const int8_t *Bh, *Bl;
    const float* bias;
    const float* binv;
    float* C;
    int N, ntile;
    if (bx < 32)      { Bh = w8h + WOFF_Q; Bl = w8l + WOFF_Q; bias = BQ; binv = winvL + ROFF_Q; C = q; N = QNc; ntile = bx; }
    else if (bx < 40) { Bh = w8h + WOFF_K; Bl = w8l + WOFF_K; bias = BK; binv = winvL + ROFF_K; C = k; N = KNc; ntile = bx - 32; }
    else              { Bh = w8h + WOFF_V; Bl = w8l + WOFF_V; bias = BV; binv = winvL + ROFF_V; C = v; N = KNc; ntile = bx - 40; }
    const int bn = ntile * 64;

    int accS1[2][4][4], accS2[2][4][4];
    #pragma unroll
    for (int mt = 0; mt < 2; mt++)
        #pragma unroll
        for (int nt = 0; nt < 4; nt++)
            #pragma unroll
            for (int r = 0; r < 4; r++) { accS1[mt][nt][r] = 0; accS2[mt][nt][r] = 0; }

    I8Ctx cx;
    i8_setup(cx, smraw, tid, Ahi, Alo, Bh, Bl, bm, bn, Hc, Hc);
    i8_mainloop(cx, accS1, accS2, Hc);

    const int lane = tid & 31;
    const int grp = lane >> 2, qd = lane & 3;
    #pragma unroll
    for (int mt = 0; mt < 2; mt++) {
        int row0 = bm + cx.m0 + mt * 16 + grp;
        int row1 = row0 + 8;
        float ai0 = ainv[row0], ai1 = ainv[row1];
        #pragma unroll
        for (int nt = 0; nt < 4; nt++) {
            int col0 = bn + cx.n0 + nt * 8 + 2 * qd;
            int col1 = col0 + 1;
            float s00 = ai0 * binv[col0], s01 = ai0 * binv[col1];
            float s10 = ai1 * binv[col0], s11 = ai1 * binv[col1];
            float b0 = bias[col0], b1 = bias[col1];
            float o00 = ((float)accS1[mt][nt][0] + (float)accS2[mt][nt][0] * 0.0078125f) * s00 + b0;
            float o01 = ((float)accS1[mt][nt][1] + (float)accS2[mt][nt][1] * 0.0078125f) * s01 + b1;
            float o10 = ((float)accS1[mt][nt][2] + (float)accS2[mt][nt][2] * 0.0078125f) * s10 + b0;
            float o11 = ((float)accS1[mt][nt][3] + (float)accS2[mt][nt][3] * 0.0078125f) * s11 + b1;
            *(float2*)(C + (size_t)row0 * N + col0) = make_float2(o00, o01);
            *(float2*)(C + (size_t)row1 * N + col0) = make_float2(o10, o11);
        }
    }
}

// ---------------- generic int8 GEMM (O / G+U / D) ----------------
__global__ __launch_bounds__(256, 2) void gemm_i8(
    const int8_t* __restrict__ Ahi, const int8_t* __restrict__ Alo,
    const float* __restrict__ ainv,
    const int8_t* __restrict__ Bh1, const int8_t* __restrict__ Bl1,
    const float* __restrict__ binv1, const float* __restrict__ resid1, float* __restrict__ C1,
    const int8_t* __restrict__ Bh2, const int8_t* __restrict__ Bl2,
    const float* __restrict__ binv2, const float* __restrict__ resid2, float* __restrict__ C2,
    int M, int N, int K) {
    extern __shared__ uint8_t smraw[];
    const int tid = threadIdx.x;
    const int bm = blockIdx.y * 128, bn = blockIdx.x * 64;

    const int8_t* Bh = Bh1; const int8_t* Bl = Bl1;
    const float* binv = binv1; const float* resid = resid1;
    float* C = C1;
    if (blockIdx.z == 1) { Bh = Bh2; Bl = Bl2; binv = binv2; resid = resid2; C = C2; }

    int accS1[2][4][4], accS2[2][4][4];
    #pragma unroll
    for (int mt = 0; mt < 2; mt++)
        #pragma unroll
        for (int nt = 0; nt < 4; nt++)
            #pragma unroll
            for (int r = 0; r < 4; r++) { accS1[mt][nt][r] = 0; accS2[mt][nt][r] = 0; }

    I8Ctx cx;
    i8_setup(cx, smraw, tid, Ahi, Alo, Bh, Bl, bm, bn, K, K);
    i8_mainloop(cx, accS1, accS2, K);

    const int lane = tid & 31;
    const int grp = lane >> 2, qd = lane & 3;
    #pragma unroll
    for (int mt = 0; mt < 2; mt++) {
        int row0 = bm + cx.m0 + mt * 16 + grp;
        int row1 = row0 + 8;
        float ai0 = ainv[row0], ai1 = ainv[row1];
        #pragma unroll
        for (int nt = 0; nt < 4; nt++) {
            int col0 = bn + cx.n0 + nt * 8 + 2 * qd;
            int col1 = col0 + 1;
            float s00 = ai0 * binv[col0], s01 = ai0 * binv[col1];
            float s10 = ai1 * binv[col0], s11 = ai1 * binv[col1];
            float o00 = ((float)accS1[mt][nt][0] + (float)accS2[mt][nt][0] * 0.0078125f) * s00;
            float o01 = ((float)accS1[mt][nt][1] + (float)accS2[mt][nt][1] * 0.0078125f) * s01;
            float o10 = ((float)accS1[mt][nt][2] + (float)accS2[mt][nt][2] * 0.0078125f) * s10;
            float o11 = ((float)accS1[mt][nt][3] + (float)accS2[mt][nt][3] * 0.0078125f) * s11;
            if (resid) {
                o00 += resid[(size_t)row0 * N + col0];
                o01 += resid[(size_t)row0 * N + col1];
                o10 += resid[(size_t)row1 * N + col0];
                o11 += resid[(size_t)row1 * N + col1];
            }
            *(float2*)(C + (size_t)row0 * N + col0) = make_float2(o00, o01);
            *(float2*)(C + (size_t)row1 * N + col0) = make_float2(o10, o11);
        }
    }
}

// ================= bf16 GEMM infra (attention only) =================
struct GemmCtx {
    const __nv_bfloat16 *pAh, *pAl, *pBh, *pBl;
    uint32_t sb, srowA, srowB;
    int lgA, swA, gB, swB;
    int m0, n0, lrow16, lch, lsw;
};

__device__ __forceinline__ void gemm_setup(GemmCtx& cx, uint8_t* smraw, int tid,
                                           const __nv_bfloat16* Ahi, const __nv_bfloat16* Alo,
                                           const __nv_bfloat16* Bhi, const __nv_bfloat16* Blo,
                                           int bm, int bn, int ldA, int ldB) {
    const int warpId = tid >> 5, lane = tid & 31;
    cx.m0 = (warpId & 3) * 32;
    cx.n0 = (warpId >> 2) * 32;
    cx.lrow16 = lane & 15;
    cx.lch = lane >> 4;
    cx.lsw = (cx.lrow16 >> 1) & 3;
    cx.sb = sptr(smraw);
    int lrowA = tid >> 1;
    cx.lgA = (tid & 1) * 2;
    cx.swA = (lrowA >> 1) & 3;
    cx.pAh = Ahi + (size_t)(bm + lrowA) * ldA;
    cx.pAl = Alo + (size_t)(bm + lrowA) * ldA;
    cx.srowA = cx.sb + lrowA * 64;
    int lrowB = tid >> 2;
    cx.gB = tid & 3;
    cx.swB = (lrowB >> 1) & 3;
    cx.pBh = Bhi + (size_t)(bn + lrowB) * ldB;
    cx.pBl = Blo + (size_t)(bn + lrowB) * ldB;
    cx.srowB = cx.sb + lrowB * 64;
}

__device__ __forceinline__ void gemm_mainloop(GemmCtx& cx, float acc[2][4][4], int K) {
    auto loadStage = [&](int st, int k0) {
        uint32_t dA = cx.srowA + st * STAGE_B;
        #pragma unroll
        for (int i = 0; i < 2; i++) {
            int g = cx.lgA + i;
            uint32_t off = (uint32_t)(g ^ cx.swA) << 4;
            CP_ASYNC16(dA + off, cx.pAh + k0 + g * 8);
            CP_ASYNC16(dA + OFF_AL + off, cx.pAl + k0 + g * 8);
        }
        uint32_t dB = cx.srowB + st * STAGE_B;
        uint32_t offb = (uint32_t)(cx.gB ^ cx.swB) << 4;
        CP_ASYNC16(dB + OFF_BH + offb, cx.pBh + k0 + cx.gB * 8);
        CP_ASYNC16(dB + OFF_BL + offb, cx.pBl + k0 + cx.gB * 8);
        CP_COMMIT();
    };
    const int KT = K >> 5;
    loadStage(0, 0);
    if (KT > 1) loadStage(1, 32);

    for (int kt = 0; kt < KT; kt++) {
        const int st = kt % NSTAGE;
        if (kt + 1 < KT) { CP_WAIT(1); } else { CP_WAIT(0); }
        __syncthreads();
        if (kt + 2 < KT) loadStage((kt + 2) % NSTAGE, (kt + 2) << 5);

        const uint32_t tAh = cx.sb + st * STAGE_B;
        const uint32_t tAl = tAh + OFF_AL;
        const uint32_t tBh = tAh + OFF_BH;
        const uint32_t tBl = tAh + OFF_BL;

        #pragma unroll
        for (int ks = 0; ks < 2; ks++) {
            const uint32_t choff = (uint32_t)(((ks * 2 + cx.lch) ^ cx.lsw)) << 4;
            uint32_t ra0 = (uint32_t)(cx.m0 + cx.lrow16) * 64 + choff;
            uint32_t ra1 = (uint32_t)(cx.m0 + 16 + cx.lrow16) * 64 + choff;
            uint32_t rb0 = (uint32_t)(cx.n0 + cx.lrow16) * 64 + choff;

            uint32_t afH[2][4], afL[2][4], bf[4][2];
            #pragma unroll
            for (int np = 0; np < 2; np++) {
                uint32_t q[4];
                ldsm4(q, tBh + rb0 + (uint32_t)(np * 16 * 64));
                bf[2 * np][0] = q[0]; bf[2 * np + 1][0] = q[1];
                bf[2 * np][1] = q[2]; bf[2 * np + 1][1] = q[3];
            }
            ldsm4(afH[0], tAh + ra0);
            ldsm4(afH[1], tAh + ra1);
            #pragma unroll
            for (int mt = 0; mt < 2; mt++)
                #pragma unroll
                for (int nt = 0; nt < 4; nt++)
                    mma_bf16(acc[mt][nt], afH[mt], bf[nt]);
            ldsm4(afL[0], tAl + ra0);
            ldsm4(afL[1], tAl + ra1);
            #pragma unroll
            for (int mt = 0; mt < 2; mt++)
                #pragma unroll
                for (int nt = 0; nt < 4; nt++)
                    mma_bf16(acc[mt][nt], afL[mt], bf[nt]);
            #pragma unroll
            for (int np = 0; np < 2; np++) {
                uint32_t q[4];
                ldsm4(q, tBl + rb0 + (uint32_t)(np * 16 * 64));
                bf[2 * np][0] = q[0]; bf[2 * np + 1][0] = q[1];
                bf[2 * np][1] = q[2]; bf[2 * np + 1][1] = q[3];
            }
            #pragma unroll
            for (int mt = 0; mt < 2; mt++)
                #pragma unroll
                for (int nt = 0; nt < 4; nt++)
                    mma_bf16(acc[mt][nt], afH[mt], bf[nt]);
        }
    }
}

// ---------------- attention scores: S = Qs * K^T (bf16x3), causal tile skip ----------------
__global__ __launch_bounds__(256, 3) void attn_scores_mma(
    const __nv_bfloat16* __restrict__ qh, const __nv_bfloat16* __restrict__ ql,
    const __nv_bfloat16* __restrict__ kh, const __nv_bfloat16* __restrict__ kl,
    float* __restrict__ scores) {
    if (blockIdx.x > 2 * blockIdx.y + 1) return;
    extern __shared__ uint8_t smraw[];
    const int tid = threadIdx.x;
    const int bh = blockIdx.z;
    const int b = bh >> 4, hd = bh & 15, kvh = hd >> 2;
    const int bm = blockIdx.y * 128, bn = blockIdx.x * 64;
    float* C = scores + (size_t)bh * Sc * Sc;

    float acc[2][4][4];
    #pragma unroll
    for (int mt = 0; mt < 2; mt++)
        #pragma unroll
        for (int nt = 0; nt < 4; nt++)
            #pragma unroll
            for (int r = 0; r < 4; r++) acc[mt][nt][r] = 0.f;

    GemmCtx cx;
    gemm_setup(cx, smraw, tid,
               qh + (size_t)b * Sc * QNc + (size_t)hd * DHc,
               ql + (size_t)b * Sc * QNc + (size_t)hd * DHc,
               kh + (size_t)b * Sc * KNc + (size_t)kvh * DHc,
               kl + (size_t)b * Sc * KNc + (size_t)kvh * DHc,
               bm, bn, QNc, KNc);
    gemm_mainloop(cx, acc, DHc);

    const int lane = tid & 31;
    const int grp = lane >> 2, qd = lane & 3;
    #pragma unroll
    for (int mt = 0; mt < 2; mt++) {
        int row0 = bm + cx.m0 + mt * 16 + grp;
        int row1 = row0 + 8;
        #pragma unroll
        for (int nt = 0; nt < 4; nt++) {
            int col = bn + cx.n0 + nt * 8 + 2 * qd;
            *(float2*)(C + (size_t)row0 * Sc + col) = make_float2(acc[mt][nt][0], acc[mt][nt][1]);
            *(float2*)(C + (size_t)row1 * Sc + col) = make_float2(acc[mt][nt][2], acc[mt][nt][3]);
        }
    }
}

// ---------------- attention context: ctx = P * V (bf16x3), fp32 out ----------------
__global__ __launch_bounds__(256, 3) void attn_ctx_mma(
    const __nv_bfloat16* __restrict__ ph, const __nv_bfloat16* __restrict__ pl,
    const __nv_bfloat16* __restrict__ vTh, const __nv_bfloat16* __restrict__ vTl,
    float* __restrict__ ctx) {
    extern __shared__ uint8_t smraw[];
    const int tid = threadIdx.x;
    const int bh = blockIdx.z;
    const int b = bh >> 4, hd = bh & 15, kvh = hd >> 2;
    const int bm = blockIdx.y * 128, bn = blockIdx.x * 64;

    float acc[2][4][4];
    #pragma unroll
    for (int mt = 0; mt < 2; mt++)
        #pragma unroll
        for (int nt = 0; nt < 4; nt++)
            #pragma unroll
            for (int r = 0; r < 4; r++) acc[mt][nt][r] = 0.f;

    GemmCtx cx;
    gemm_setup(cx, smraw, tid,
               ph + (size_t)bh * Sc * Sc,
               pl + (size_t)bh * Sc * Sc,
               vTh + ((size_t)b * KNc + (size_t)kvh * DHc) * Sc,
               vTl + ((size_t)b * KNc + (size_t)kvh * DHc) * Sc,
               bm, bn, Sc, Sc);
    gemm_mainloop(cx, acc, ((bm >> 5) + 4) << 5);

    const int lane = tid & 31;
    const int grp = lane >> 2, qd = lane & 3;
    #pragma unroll
    for (int mt = 0; mt < 2; mt++) {
        int lr0 = cx.m0 + mt * 16 + grp;
        #pragma unroll
        for (int half = 0; half < 2; half++) {
            int row = bm + lr0 + half * 8;
            size_t base = ((size_t)(b * Sc + row)) * QNc + (size_t)hd * DHc;
            #pragma unroll
            for (int nt = 0; nt < 4; nt++) {
                int col = bn + cx.n0 + nt * 8 + 2 * qd;
                *(float2*)(ctx + base + col) =
                    make_float2(acc[mt][nt][half * 2 + 0], acc[mt][nt][half * 2 + 1]);
            }
        }
    }
}

// ---------------- RoPE (q+k fused), table-driven, + scale + bf16 hi/lo split ----------------
__global__ void rope_split2_kernel(const float* __restrict__ qb, const float* __restrict__ kb,
                                   const float* __restrict__ rc, const float* __restrict__ rs,
                                   __nv_bfloat16* __restrict__ qh, __nv_bfloat16* __restrict__ ql,
                                   __nv_bfloat16* __restrict__ kh, __nv_bfloat16* __restrict__ kl) {
    int token = blockIdx.x;
    int head  = blockIdx.y;
    int d = threadIdx.x;
    int s = token % Sc;
    const float* p;
    __nv_bfloat16 *oh, *ol;
    size_t idx;
    float scale;
    if (head < NHc) {
        p = qb + ((size_t)token * NHc + head) * DHc;
        idx = ((size_t)token * NHc + head) * DHc;
        oh = qh; ol = ql; scale = INV_SQRT_DH;
    } else {
        int h2 = head - NHc;
        p = kb + ((size_t)token * NKVc + h2) * DHc;
        idx = ((size_t)token * NKVc + h2) * DHc;
        oh = kh; ol = kl; scale = 1.0f;
    }
    float cs = rc[s * 64 + d];
    float sn = rs[s * 64 + d];
    float x1 = p[d], x2 = p[d + 64];
    float v0 = (x1 * cs - x2 * sn) * scale;
    float v1 = (x2 * cs + x1 * sn) * scale;
    __nv_bfloat16 h0 = __float2bfloat16(v0);
    __nv_bfloat16 h1 = __float2bfloat16(v1);
    oh[idx + d]      = h0;
    ol[idx + d]      = __float2bfloat16(v0 - __bfloat162float(h0));
    oh[idx + d + 64] = h1;
    ol[idx + d + 64] = __float2bfloat16(v1 - __bfloat162float(h1));
}

// ---------------- V transpose + split ----------------
__global__ void vsplitT_kernel(const float* __restrict__ v,
                               __nv_bfloat16* __restrict__ vTh,
                               __nv_bfloat16* __restrict__ vTl) {
    __shared__ float tile[32][33];
    int b = blockIdx.z;
    int t0 = blockIdx.x * 32, d0 = blockIdx.y * 32;
    int tx = threadIdx.x, ty = threadIdx.y;
    for (int i = ty; i < 32; i += 8)
        tile[i][tx] = v[(size_t)(b * Sc + t0 + i) * KNc + d0 + tx];
    __syncthreads();
    for (int i = ty; i < 32; i += 8) {
        float val = tile[tx][i];
        size_t idx = ((size_t)b * KNc + d0 + i) * Sc + t0 + tx;
        __nv_bfloat16 hb = __float2bfloat16(val);
        vTh[idx] = hb;
        vTl[idx] = __float2bfloat16(val - __bfloat162float(hb));
    }
}

// ---------------- masked softmax -> bf16 hi/lo P ----------------
__global__ void softmax_kernel(const float* __restrict__ scores, const int* __restrict__ mask,
                               __nv_bfloat16* __restrict__ ph, __nv_bfloat16* __restrict__ pl) {
    int row = blockIdx.x;
    int qpos = row % Sc;
    int b = row / (NHc * Sc);
    const float* r = scores + (size_t)row * Sc;
    int t = threadIdx.x;
    float v[4];
    float mx = -3.0e38f;
    #pragma unroll
    for (int i = 0; i < 4; i++) {
        int k = t + 128 * i;
        bool ok = (k <= qpos) && (mask[b * Sc + k] > 0);
        v[i] = ok ? r[k] : -1e30f;
        mx = fmaxf(mx, v[i]);
    }
    __shared__ float sh[128];
    sh[t] = mx; __syncthreads();
    for (int o = 64; o; o >>= 1) { if (t < o) sh[t] = fmaxf(sh[t], sh[t + o]); __syncthreads(); }
    mx = sh[0]; __syncthreads();
    float sm = 0.f;
    #pragma unroll
    for (int i = 0; i < 4; i++) { v[i] = expf(v[i] - mx); sm += v[i]; }
    sh[t] = sm; __syncthreads();
    for (int o = 64; o; o >>= 1) { if (t < o) sh[t] += sh[t + o]; __syncthreads(); }
    float inv = 1.0f / sh[0];
    #pragma unroll
    for (int i = 0; i < 4; i++) {
        float p = v[i] * inv;
        __nv_bfloat16 hb = __float2bfloat16(p);
        ph[(size_t)row * Sc + t + 128 * i] = hb;
        pl[(size_t)row * Sc + t + 128 * i] = __float2bfloat16(p - __bfloat162float(hb));
    }
}

// ---------------- silu(g)*u -> g fp32 ----------------
__global__ void silu_mul_kernel(float* __restrict__ g, const float* __restrict__ u, int n) {
    int i = blockIdx.x * 256 + threadIdx.x;
    if (i < n) {
        float x = g[i];
        g[i] = (x / (1.0f + expf(-x))) * u[i];
    }
}

// ---------------- final pooling + rmsnorm(lnf) ----------------
__global__ void pool_kernel(const float* __restrict__ h, const int* __restrict__ mask,
                            const float* __restrict__ lnf, float* __restrict__ pooled) {
    int b = blockIdx.x;
    int t = threadIdx.x;
    __shared__ float sh[256];
    int cnt = 0;
    for (int i = t; i < Sc; i += 256) cnt += mask[b * Sc + i];
    sh[t] = (float)cnt; __syncthreads();
    for (int o = 128; o; o >>= 1) { if (t < o) sh[t] += sh[t + o]; __syncthreads(); }
    int last = (int)sh[0] - 1;
    __syncthreads();
    const float* row = h + ((size_t)b * Sc + last) * Hc;
    float ss = 0.f;
    for (int i = t; i < Hc; i += 256) { float x = row[i]; ss += x * x; }
    sh[t] = ss; __syncthreads();
    for (int o = 128; o; o >>= 1) { if (t < o) sh[t] += sh[t + o]; __syncthreads(); }
    float sc = rsqrtf(sh[0] / (float)Hc + 1e-6f);
    for (int i = t; i < Hc; i += 256) pooled[b * Hc + i] = row[i] * sc * lnf[i];
}

// ---------------- classifier ----------------
__global__ void cls1_kernel(const float* __restrict__ pooled, const float* __restrict__ cw1,
                            const float* __restrict__ cb1, float* __restrict__ hid) {
    int n = blockIdx.x * 128 + threadIdx.x;
    int b = blockIdx.y;
    float acc = cb1[n];
    const float* p = pooled + (size_t)b * Hc;
    for (int k = 0; k < Hc; k++) acc += p[k] * cw1[(size_t)k * Hc + n];
    hid[(size_t)b * Hc + n] = fmaxf(acc, 0.f);
}

__global__ void cls2_kernel(const float* __restrict__ hid, const float* __restrict__ cw2,
                            const float* __restrict__ cb2, float* __restrict__ out) {
    int b = blockIdx.x >> 1, c = blockIdx.x & 1;
    float acc = 0.f;
    for (int k = threadIdx.x; k < Hc; k += 128) acc += hid[(size_t)b * Hc + k] * cw2[k * NCc + c];
    __shared__ float sh[128];
    sh[threadIdx.x] = acc; __syncthreads();
    for (int o = 64; o; o >>= 1) { if (threadIdx.x < o) sh[threadIdx.x] += sh[threadIdx.x + o]; __syncthreads(); }
    if (threadIdx.x == 0) out[b * NCc + c] = sh[0] + cb2[c];
}

// ---------------- host orchestration ----------------
extern "C" void kernel_launch(void* const* d_in, const int* in_sizes, int n_in,
                              void* d_out, int out_size) {
    (void)in_sizes; (void)n_in; (void)out_size;
    const int*   ids   = (const int*)d_in[0];
    const int*   mask  = (const int*)d_in[1];
    const float* embed = (const float*)d_in[2];
    const float* ln1   = (const float*)d_in[3];
    const float* wq    = (const float*)d_in[4];
    const float* bq    = (const float*)d_in[5];
    const float* wk    = (const float*)d_in[6];
    const float* bk    = (const float*)d_in[7];
    const float* wv    = (const float*)d_in[8];
    const float* bv    = (const float*)d_in[9];
    const float* wo    = (const float*)d_in[10];
    const float* laq   = (const float*)d_in[11];
    const float* lbq   = (const float*)d_in[12];
    const float* lak   = (const float*)d_in[13];
    const float* lbk   = (const float*)d_in[14];
    const float* lav   = (const float*)d_in[15];
    const float* lbv   = (const float*)d_in[16];
    const float* lao   = (const float*)d_in[17];
    const float* lbo   = (const float*)d_in[18];
    const float* ln2   = (const float*)d_in[19];
    const float* wg    = (const float*)d_in[20];
    const float* wu    = (const float*)d_in[21];
    const float* wd    = (const float*)d_in[22];
    const float* lnf   = (const float*)d_in[23];
    const float* cw1   = (const float*)d_in[24];
    const float* cb1   = (const float*)d_in[25];
    const float* cw2   = (const float*)d_in[26];
    const float* cb2   = (const float*)d_in[27];
    float* out = (float*)d_out;

    cudaFuncSetAttribute(gemm_qkv_i8, cudaFuncAttributeMaxDynamicSharedMemorySize, GEMM_SMEM);
    cudaFuncSetAttribute(gemm_i8, cudaFuncAttributeMaxDynamicSharedMemorySize, GEMM_SMEM);
    cudaFuncSetAttribute(attn_scores_mma, cudaFuncAttributeMaxDynamicSharedMemorySize, GEMM_SMEM);
    cudaFuncSetAttribute(attn_ctx_mma, cudaFuncAttributeMaxDynamicSharedMemorySize, GEMM_SMEM);

    float *h, *q, *k, *v, *sc, *ctx, *g, *u, *pooled, *cls, *rc, *rs;
    float *xinv, *cinv, *ginv, *winv, *wt;
    int8_t *x8h, *x8l, *c8h, *c8l, *g8h, *g8l, *w8h, *w8l;
    __nv_bfloat16 *qh, *ql, *kh, *kl, *vTh, *vTl, *ph, *pl;
    cudaGetSymbolAddress((void**)&h,   d_h);
    cudaGetSymbolAddress((void**)&x8h, d_x8h);
    cudaGetSymbolAddress((void**)&x8l, d_x8l);
    cudaGetSymbolAddress((void**)&xinv, d_xinv);
    cudaGetSymbolAddress((void**)&q,   d_q);
    cudaGetSymbolAddress((void**)&k,   d_k);
    cudaGetSymbolAddress((void**)&v,   d_v);
    cudaGetSymbolAddress((void**)&qh,  d_qh);
    cudaGetSymbolAddress((void**)&ql,  d_ql);
    cudaGetSymbolAddress((void**)&kh,  d_kh);
    cudaGetSymbolAddress((void**)&kl,  d_kl);
    cudaGetSymbolAddress((void**)&vTh, d_vTh);
    cudaGetSymbolAddress((void**)&vTl, d_vTl);
    cudaGetSymbolAddress((void**)&rc,  d_ropec);
    cudaGetSymbolAddress((void**)&rs,  d_ropes);
    cudaGetSymbolAddress((void**)&sc,  d_sc);
    cudaGetSymbolAddress((void**)&ph,  d_ph);
    cudaGetSymbolAddress((void**)&pl,  d_pl);
    cudaGetSymbolAddress((void**)&ctx, d_ctx);
    cudaGetSymbolAddress((void**)&c8h, d_c8h);
    cudaGetSymbolAddress((void**)&c8l, d_c8l);
    cudaGetSymbolAddress((void**)&cinv, d_cinv);
    cudaGetSymbolAddress((void**)&g,   d_g);
    cudaGetSymbolAddress((void**)&u,   d_u);
    cudaGetSymbolAddress((void**)&g8h, d_g8h);
    cudaGetSymbolAddress((void**)&g8l, d_g8l);
    cudaGetSymbolAddress((void**)&ginv, d_ginv);
    cudaGetSymbolAddress((void**)&pooled, d_pooled);
    cudaGetSymbolAddress((void**)&cls,    d_cls);
    cudaGetSymbolAddress((void**)&wt,     d_wt);
    cudaGetSymbolAddress((void**)&w8h,    d_w8h);
    cudaGetSymbolAddress((void**)&w8l,    d_w8l);
    cudaGetSymbolAddress((void**)&winv,   d_winv);

    // ---- preprocessing: fold+transpose -> rowmax -> int8 quantize ----
    wfoldT_kernel<<<Lc * TILES_PER_LAYER, dim3(32, 8)>>>(
        wq, wk, wv, wo, wg, wu, wd,
        laq, lbq, lak, lbk, lav, lbv, lao, lbo, wt);
    wmax_kernel<<<Lc * ROWS_PER_LAYER, 256>>>(wt, winv);
    {
        size_t total4 = (size_t)Lc * LAYER_W / 4;
        wquant_kernel<<<(unsigned)((total4 + 255) / 256), 256>>>(wt, winv, w8h, w8l);
    }
    rope_table_kernel<<<Sc, 64>>>(rc, rs);
    embed_kernel<<<MTc, 256>>>(ids, embed, h);

    for (int l = 0; l < Lc; l++) {
        size_t lw = (size_t)l * LAYER_W;
        const float* winvL = winv + (size_t)l * ROWS_PER_LAYER;
        const float* LN1 = ln1 + (size_t)l * Hc;
        const float* BQ = bq + (size_t)l * QNc;
        const float* BK = bk + (size_t)l * KNc;
        const float* BV = bv + (size_t)l * KNc;
        const float* LN2 = ln2 + (size_t)l * Hc;

        rmsnorm_q8<<<MTc, 256>>>(h, LN1, x8h, x8l, xinv);

        gemm_qkv_i8<<<dim3(48, MTc / 128), 256, GEMM_SMEM>>>(
            x8h, x8l, xinv, w8h + lw, w8l + lw, winvL, BQ, BK, BV, q, k, v);

        rope_split2_kernel<<<dim3(MTc, NHc + NKVc), 64>>>(q, k, rc, rs, qh, ql, kh, kl);
        vsplitT_kernel<<<dim3(16, 16, Bc), dim3(32, 8)>>>(v, vTh, vTl);

        attn_scores_mma<<<dim3(8, 4, Bc * NHc), 256, GEMM_SMEM>>>(qh, ql, kh, kl, sc);
        softmax_kernel<<<Bc * NHc * Sc, 128>>>(sc, mask, ph, pl);
        attn_ctx_mma<<<dim3(2, 4, Bc * NHc), 256, GEMM_SMEM>>>(ph, pl, vTh, vTl, ctx);

        quant8_rows<<<MTc, 256>>>(ctx, QNc, c8h, c8l, cinv);
        gemm_i8<<<dim3(Hc / 64, MTc / 128, 1), 256, GEMM_SMEM>>>(
            c8h, c8l, cinv,
            w8h + lw + WOFF_O, w8l + lw + WOFF_O, winvL + ROFF_O, h, h,
            nullptr, nullptr, nullptr, nullptr, nullptr,
            MTc, Hc, QNc);

        rmsnorm_q8<<<MTc, 256>>>(h, LN2, x8h, x8l, xinv);
        gemm_i8<<<dim3(Fc / 64, MTc / 128, 2), 256, GEMM_SMEM>>>(
            x8h, x8l, xinv,
            w8h + lw + WOFF_G, w8l + lw + WOFF_G, winvL + ROFF_G, nullptr, g,
            w8h + lw + WOFF_U, w8l + lw + WOFF_U, winvL + ROFF_U, nullptr, u,
            MTc, Fc, Hc);
        silu_mul_kernel<<<(MTc * Fc) / 256, 256>>>(g, u, MTc * Fc);
        quant8_rows<<<MTc, 256>>>(g, Fc, g8h, g8l, ginv);
        gemm_i8<<<dim3(Hc / 64, MTc / 128, 1), 256, GEMM_SMEM>>>(
            g8h, g8l, ginv,
            w8h + lw + WOFF_D, w8l + lw + WOFF_D, winvL + ROFF_D, h, h,
            nullptr, nullptr, nullptr, nullptr, nullptr,
            MTc, Hc, Fc);
    }

    pool_kernel<<<Bc, 256>>>(h, mask, lnf, pooled);
    cls1_kernel<<<dim3(Hc / 128, Bc), 128>>>(pooled, cw1, cb1, cls);
    cls2_kernel<<<Bc * NCc, 128>>>(cls, cw2, cb2, out);
}

// round 16
// speedup vs baseline: 2.0465x; 2.0465x over previous
#include <cuda_runtime.h>
#include <cuda_bf16.h>
#include <cstddef>
#include <cstdint>
#include <math.h>

// ---------------- problem constants ----------------
#define Lc   4
#define Hc   2048
#define NHc  16
#define NKVc 4
#define DHc  128
#define Fc   5632
#define Rc   16
#define Bc   4
#define Sc   512
#define NCc  2
#define MTc  (Bc * Sc)          // 2048 tokens
#define QNc  (NHc * DHc)        // 2048
#define KNc  (NKVc * DHc)       // 512
#define LORA_SCALE 2.0f
#define INV_SQRT_DH 0.08838834764831845f

// per-layer transposed weight buffer offsets (elements)
#define WOFF_Q 0
#define WOFF_K (WOFF_Q + Hc * QNc)
#define WOFF_V (WOFF_K + Hc * KNc)
#define WOFF_O (WOFF_V + Hc * KNc)
#define WOFF_G (WOFF_O + QNc * Hc)
#define WOFF_U (WOFF_G + Hc * Fc)
#define WOFF_D (WOFF_U + Hc * Fc)
#define LAYER_W (WOFF_D + Fc * Hc)   // 45,088,768

// ---------------- scratch (static device memory; allocation-free) ----------------
__device__ float          d_h[MTc * Hc];
__device__ __nv_bfloat16  d_xh[MTc * Hc];
__device__ __nv_bfloat16  d_xl[MTc * Hc];
__device__ float          d_q[MTc * QNc];
__device__ float          d_k[MTc * KNc];
__device__ float          d_v[MTc * KNc];
__device__ __nv_bfloat16  d_qh[MTc * QNc];
__device__ __nv_bfloat16  d_ql[MTc * QNc];
__device__ __nv_bfloat16  d_kh[MTc * KNc];
__device__ __nv_bfloat16  d_kl[MTc * KNc];
__device__ __nv_bfloat16  d_vTh[Bc * KNc * Sc];
__device__ __nv_bfloat16  d_vTl[Bc * KNc * Sc];
__device__ float          d_ropec[Sc * 64];
__device__ float          d_ropes[Sc * 64];
__device__ float          d_sc[Bc * NHc * Sc * Sc];
__device__ __nv_bfloat16  d_ph[Bc * NHc * Sc * Sc];
__device__ __nv_bfloat16  d_pl[Bc * NHc * Sc * Sc];
__device__ __nv_bfloat16  d_ch[MTc * QNc];
__device__ __nv_bfloat16  d_cl[MTc * QNc];
__device__ float          d_g[MTc * Fc];
__device__ float          d_u[MTc * Fc];
__device__ __nv_bfloat16  d_gh[MTc * Fc];
__device__ __nv_bfloat16  d_gl[MTc * Fc];
__device__ float          d_pooled[Bc * Hc];
__device__ float          d_cls[Bc * Hc];
__device__ __nv_bfloat16  d_whT[(size_t)Lc * LAYER_W];  // hi weights (lora folded), [N,K]
__device__ __nv_bfloat16  d_wlT[(size_t)Lc * LAYER_W];  // lo weights, [N,K]

// ---------------- PTX helpers ----------------
__device__ __forceinline__ uint32_t sptr(const void* p) {
    return (uint32_t)__cvta_generic_to_shared(p);
}
#define CP_ASYNC16(dst, src) asm volatile("cp.async.cg.shared.global [%0], [%1], 16;\n" :: "r"(dst), "l"(src))
#define CP_COMMIT()          asm volatile("cp.async.commit_group;\n" ::: "memory")
#define CP_WAIT(n)           asm volatile("cp.async.wait_group %0;\n" :: "n"(n) : "memory")

__device__ __forceinline__ void mma_bf16(float* c, const uint32_t* a, const uint32_t* b) {
    asm volatile(
        "mma.sync.aligned.m16n8k16.row.col.f32.bf16.bf16.f32 "
        "{%0,%1,%2,%3}, {%4,%5,%6,%7}, {%8,%9}, {%0,%1,%2,%3};\n"
        : "+f"(c[0]), "+f"(c[1]), "+f"(c[2]), "+f"(c[3])
        : "r"(a[0]), "r"(a[1]), "r"(a[2]), "r"(a[3]), "r"(b[0]), "r"(b[1]));
}

__device__ __forceinline__ void ldsm4(uint32_t* r, uint32_t addr) {
    asm volatile("ldmatrix.sync.aligned.m8n8.x4.shared.b16 {%0,%1,%2,%3}, [%4];"
        : "=r"(r[0]), "=r"(r[1]), "=r"(r[2]), "=r"(r[3]) : "r"(addr));
}

// ---------------- ALL weights: transpose + LoRA fold + bf16 split, ONE launch ----------------
#define TILES_PER_LAYER 22016
__global__ void wsplit_all_kernel(const float* __restrict__ wq, const float* __restrict__ wk,
                                  const float* __restrict__ wv, const float* __restrict__ wo,
                                  const float* __restrict__ wg, const float* __restrict__ wu,
                                  const float* __restrict__ wd,
                                  const float* __restrict__ laq, const float* __restrict__ lbq,
                                  const float* __restrict__ lak, const float* __restrict__ lbk,
                                  const float* __restrict__ lav, const float* __restrict__ lbv,
                                  const float* __restrict__ lao, const float* __restrict__ lbo,
                                  __nv_bfloat16* __restrict__ hiT,
                                  __nv_bfloat16* __restrict__ loT) {
    int l = blockIdx.x / TILES_PER_LAYER;
    int r = blockIdx.x % TILES_PER_LAYER;
    const float* src; size_t woff; int K, N, tidx;
    const float* loA = nullptr; const float* loB = nullptr;
    if (r < 2048)       { src = wq + (size_t)l * Hc * QNc; woff = WOFF_Q; K = Hc;  N = QNc; tidx = r;
                          loA = laq + (size_t)l * Rc * Hc;  loB = lbq + (size_t)l * QNc * Rc; }
    else if (r < 2560)  { src = wk + (size_t)l * Hc * KNc; woff = WOFF_K; K = Hc;  N = KNc; tidx = r - 2048;
                          loA = lak + (size_t)l * Rc * Hc;  loB = lbk + (size_t)l * KNc * Rc; }
    else if (r < 3072)  { src = wv + (size_t)l * Hc * KNc; woff = WOFF_V; K = Hc;  N = KNc; tidx = r - 2560;
                          loA = lav + (size_t)l * Rc * Hc;  loB = lbv + (size_t)l * KNc * Rc; }
    else if (r < 5120)  { src = wo + (size_t)l * QNc * Hc; woff = WOFF_O; K = QNc; N = Hc;  tidx = r - 3072;
                          loA = lao + (size_t)l * Rc * QNc; loB = lbo + (size_t)l * Hc * Rc; }
    else if (r < 10752) { src = wg + (size_t)l * Hc * Fc;  woff = WOFF_G; K = Hc;  N = Fc;  tidx = r - 5120; }
    else if (r < 16384) { src = wu + (size_t)l * Hc * Fc;  woff = WOFF_U; K = Hc;  N = Fc;  tidx = r - 10752; }
    else                { src = wd + (size_t)l * Fc * Hc;  woff = WOFF_D; K = Fc;  N = Hc;  tidx = r - 16384; }
    woff += (size_t)l * LAYER_W;
    int nt = N / 32;
    int k0 = (tidx / nt) * 64, n0 = (tidx % nt) * 32;

    __shared__ float tile[64][33];   // [k][n]
    __shared__ float sA[16][64];     // lora A[r][k-local]
    __shared__ float sB[32][17];     // lora B[n-local][r]
    int tx = threadIdx.x, ty = threadIdx.y;   // (32, 8)
    int tid = ty * 32 + tx;
    for (int i = ty; i < 64; i += 8)
        tile[i][tx] = src[(size_t)(k0 + i) * N + n0 + tx];
    if (loA) {
        for (int idx = tid; idx < 1024; idx += 256) {
            int rr = idx >> 6, kk = idx & 63;
            sA[rr][kk] = loA[(size_t)rr * K + k0 + kk];
        }
        for (int idx = tid; idx < 512; idx += 256) {
            int nn = idx >> 4, rr = idx & 15;
            sB[nn][rr] = loB[(size_t)(n0 + nn) * Rc + rr];
        }
    }
    __syncthreads();
    for (int i = ty; i < 32; i += 8) {
        float v0 = tile[2 * tx][i], v1 = tile[2 * tx + 1][i];
        if (loA) {
            float d0 = 0.f, d1 = 0.f;
            #pragma unroll
            for (int rr = 0; rr < Rc; rr++) {
                float bb = sB[i][rr];
                d0 += sA[rr][2 * tx] * bb;
                d1 += sA[rr][2 * tx + 1] * bb;
            }
            v0 += LORA_SCALE * d0;
            v1 += LORA_SCALE * d1;
        }
        __nv_bfloat16 h0 = __float2bfloat16(v0), h1 = __float2bfloat16(v1);
        __nv_bfloat162 hv; hv.x = h0; hv.y = h1;
        __nv_bfloat162 lv;
        lv.x = __float2bfloat16(v0 - __bfloat162float(h0));
        lv.y = __float2bfloat16(v1 - __bfloat162float(h1));
        size_t idx = woff + (size_t)(n0 + i) * K + k0 + 2 * tx;
        *(__nv_bfloat162*)(hiT + idx) = hv;
        *(__nv_bfloat162*)(loT + idx) = lv;
    }
}

// ---------------- RoPE table precompute ----------------
__global__ void rope_table_kernel(float* __restrict__ rc, float* __restrict__ rs) {
    int s = blockIdx.x;
    int d = threadIdx.x;
    float freq = powf(1000000.0f, -(float)d / 64.0f);
    float ang = (float)s * freq;
    float sn, cs;
    sincosf(ang, &sn, &cs);
    rc[s * 64 + d] = cs;
    rs[s * 64 + d] = sn;
}

// ---------------- embedding gather ----------------
__global__ void embed_kernel(const int* __restrict__ ids,
                             const float* __restrict__ emb,
                             float* __restrict__ h) {
    int row = blockIdx.x;
    const float* src = emb + (size_t)ids[row] * Hc;
    float* dst = h + (size_t)row * Hc;
    for (int i = threadIdx.x; i < Hc; i += 256) dst[i] = src[i];
}

// ---------------- rmsnorm: bf16 hi/lo split only ----------------
__global__ void rmsnorm_kernel(const float* __restrict__ in,
                               const float* __restrict__ w,
                               __nv_bfloat16* __restrict__ oh,
                               __nv_bfloat16* __restrict__ ol) {
    int row = blockIdx.x;
    const float* x = in + (size_t)row * Hc;
    float ss = 0.f;
    for (int i = threadIdx.x; i < Hc; i += 256) { float v = x[i]; ss += v * v; }
    __shared__ float sh[256];
    sh[threadIdx.x] = ss; __syncthreads();
    for (int o = 128; o; o >>= 1) { if (threadIdx.x < o) sh[threadIdx.x] += sh[threadIdx.x + o]; __syncthreads(); }
    float sc = rsqrtf(sh[0] / (float)Hc + 1e-6f);
    for (int i = threadIdx.x; i < Hc; i += 256) {
        float v = x[i] * sc * w[i];
        __nv_bfloat16 hb = __float2bfloat16(v);
        oh[(size_t)row * Hc + i] = hb;
        ol[(size_t)row * Hc + i] = __float2bfloat16(v - __bfloat162float(hb));
    }
}

// ================= shared GEMM mainloop (macro-free inline function) =================
#define TILE_B 8192                  // 128 * 64B
#define STAGE_B (4 * TILE_B)         // Ah, Al, Bh, Bl = 32KB
#define NSTAGE 3
#define GEMM_SMEM (NSTAGE * STAGE_B) // 96KB

struct GemmCtx {
    const __nv_bfloat16 *pAh, *pAl, *pBh, *pBl;
    uint32_t sb, srow;
    int lg0, lswz;
    int m0, n0, lrow16, lch, lsw;
};

__device__ __forceinline__ void gemm_mainloop(GemmCtx& cx, float acc[2][8][4], int K) {
    auto loadStage = [&](int st, int k0) {
        uint32_t d = cx.srow + st * STAGE_B;
        #pragma unroll
        for (int i = 0; i < 2; i++) {
            int g = cx.lg0 + i;
            uint32_t off = (uint32_t)(g ^ cx.lswz) << 4;
            CP_ASYNC16(d + 0 * TILE_B + off, cx.pAh + k0 + g * 8);
            CP_ASYNC16(d + 1 * TILE_B + off, cx.pAl + k0 + g * 8);
            CP_ASYNC16(d + 2 * TILE_B + off, cx.pBh + k0 + g * 8);
            CP_ASYNC16(d + 3 * TILE_B + off, cx.pBl + k0 + g * 8);
        }
        CP_COMMIT();
    };
    const int KT = K >> 5;
    loadStage(0, 0);
    if (KT > 1) loadStage(1, 32);

    for (int kt = 0; kt < KT; kt++) {
        const int st = kt % NSTAGE;
        if (kt + 1 < KT) { CP_WAIT(1); } else { CP_WAIT(0); }
        __syncthreads();
        if (kt + 2 < KT) loadStage((kt + 2) % NSTAGE, (kt + 2) << 5);

        const uint32_t tAh = cx.sb + st * STAGE_B;
        const uint32_t tAl = tAh + TILE_B;
        const uint32_t tBh = tAh + 2 * TILE_B;
        const uint32_t tBl = tAh + 3 * TILE_B;

        #pragma unroll
        for (int ks = 0; ks < 2; ks++) {
            const uint32_t choff = (uint32_t)(((ks * 2 + cx.lch) ^ cx.lsw)) << 4;
            uint32_t ra0 = (uint32_t)(cx.m0 + cx.lrow16) * 64 + choff;
            uint32_t ra1 = (uint32_t)(cx.m0 + 16 + cx.lrow16) * 64 + choff;
            uint32_t rb0 = (uint32_t)(cx.n0 + cx.lrow16) * 64 + choff;

            uint32_t afH[2][4], afL[2][4], bf[8][2];
            #pragma unroll
            for (int np = 0; np < 4; np++) {
                uint32_t q[4];
                ldsm4(q, tBh + rb0 + (uint32_t)(np * 16 * 64));
                bf[2 * np][0] = q[0]; bf[2 * np + 1][0] = q[1];
                bf[2 * np][1] = q[2]; bf[2 * np + 1][1] = q[3];
            }
            ldsm4(afH[0], tAh + ra0);
            ldsm4(afH[1], tAh + ra1);
            #pragma unroll
            for (int mt = 0; mt < 2; mt++)
                #pragma unroll
                for (int nt = 0; nt < 8; nt++)
                    mma_bf16(acc[mt][nt], afH[mt], bf[nt]);
            ldsm4(afL[0], tAl + ra0);
            ldsm4(afL[1], tAl + ra1);
            #pragma unroll
            for (int mt = 0; mt < 2; mt++)
                #pragma unroll
                for (int nt = 0; nt < 8; nt++)
                    mma_bf16(acc[mt][nt], afL[mt], bf[nt]);
            #pragma unroll
            for (int np = 0; np < 4; np++) {
                uint32_t q[4];
                ldsm4(q, tBl + rb0 + (uint32_t)(np * 16 * 64));
                bf[2 * np][0] = q[0]; bf[2 * np + 1][0] = q[1];
                bf[2 * np][1] = q[2]; bf[2 * np + 1][1] = q[3];
            }
            #pragma unroll
            for (int mt = 0; mt < 2; mt++)
                #pragma unroll
                for (int nt = 0; nt < 8; nt++)
                    mma_bf16(acc[mt][nt], afH[mt], bf[nt]);
        }
    }
}

__device__ __forceinline__ void gemm_setup(GemmCtx& cx, uint8_t* smraw, int tid,
                                           const __nv_bfloat16* Ahi, const __nv_bfloat16* Alo,
                                           const __nv_bfloat16* Bhi, const __nv_bfloat16* Blo,
                                           int bm, int bn, int K) {
    const int warpId = tid >> 5, lane = tid & 31;
    cx.m0 = (warpId & 3) * 32;
    cx.n0 = (warpId >> 2) * 64;
    cx.lrow16 = lane & 15;
    cx.lch = lane >> 4;
    cx.lsw = (cx.lrow16 >> 1) & 3;
    cx.sb = sptr(smraw);
    int lrow = tid >> 1;
    cx.lg0 = (tid & 1) * 2;
    cx.lswz = (lrow >> 1) & 3;
    cx.pAh = Ahi + (size_t)(bm + lrow) * K;
    cx.pAl = Alo + (size_t)(bm + lrow) * K;
    cx.pBh = Bhi + (size_t)(bn + lrow) * K;
    cx.pBl = Blo + (size_t)(bn + lrow) * K;
    cx.srow = cx.sb + lrow * 64;
}

// ---------------- fused QKV GEMM: 24 N-tiles (16 Q + 4 K + 4 V) x 16 M-tiles ----------------
__global__ __launch_bounds__(256, 2) void gemm_qkv(
    const __nv_bfloat16* __restrict__ Ahi, const __nv_bfloat16* __restrict__ Alo,
    const __nv_bfloat16* __restrict__ WQh, const __nv_bfloat16* __restrict__ WQl,
    const __nv_bfloat16* __restrict__ WKh, const __nv_bfloat16* __restrict__ WKl,
    const __nv_bfloat16* __restrict__ WVh, const __nv_bfloat16* __restrict__ WVl,
    const float* __restrict__ BQ, const float* __restrict__ BK, const float* __restrict__ BV,
    float* __restrict__ q, float* __restrict__ k, float* __restrict__ v) {
    extern __shared__ uint8_t smraw[];
    const int tid = threadIdx.x;
    const int bx = blockIdx.x;
    const int bm = blockIdx.y * 128;

    const __nv_bfloat16 *Bhi, *Blo;
    const float* bias;
    float* C;
    int N, ntile;
    if (bx < 16)      { Bhi = WQh; Blo = WQl; bias = BQ; C = q; N = QNc; ntile = bx; }
    else if (bx < 20) { Bhi = WKh; Blo = WKl; bias = BK; C = k; N = KNc; ntile = bx - 16; }
    else              { Bhi = WVh; Blo = WVl; bias = BV; C = v; N = KNc; ntile = bx - 20; }
    const int bn = ntile * 128;

    float acc[2][8][4];
    #pragma unroll
    for (int mt = 0; mt < 2; mt++)
        #pragma unroll
        for (int nt = 0; nt < 8; nt++)
            #pragma unroll
            for (int r = 0; r < 4; r++) acc[mt][nt][r] = 0.f;

    GemmCtx cx;
    gemm_setup(cx, smraw, tid, Ahi, Alo, Bhi, Blo, bm, bn, Hc);
    gemm_mainloop(cx, acc, Hc);

    const int lane = tid & 31;
    const int grp = lane >> 2, qd = lane & 3;
    #pragma unroll
    for (int mt = 0; mt < 2; mt++) {
        int row0 = bm + cx.m0 + mt * 16 + grp;
        int row1 = row0 + 8;
        #pragma unroll
        for (int nt = 0; nt < 8; nt++) {
            int lc0 = cx.n0 + nt * 8 + 2 * qd;
            int col0 = bn + lc0, col1 = col0 + 1;
            float b0 = bias[col0], b1 = bias[col1];
            *(float2*)(C + (size_t)row0 * N + col0) =
                make_float2(acc[mt][nt][0] + b0, acc[mt][nt][1] + b1);
            *(float2*)(C + (size_t)row1 * N + col0) =
                make_float2(acc[mt][nt][2] + b0, acc[mt][nt][3] + b1);
        }
    }
}

// ---------------- generic bf16x3 GEMM (O / G+U / D) ----------------
__global__ __launch_bounds__(256, 2) void gemm_bf16x3(
    const __nv_bfloat16* __restrict__ Ahi, const __nv_bfloat16* __restrict__ Alo,
    const __nv_bfloat16* __restrict__ Bhi1, const __nv_bfloat16* __restrict__ Blo1,
    const float* __restrict__ resid1, float* __restrict__ C1,
    const __nv_bfloat16* __restrict__ Bhi2, const __nv_bfloat16* __restrict__ Blo2,
    const float* __restrict__ resid2, float* __restrict__ C2,
    int M, int N, int K) {
    extern __shared__ uint8_t smraw[];
    const int tid = threadIdx.x;
    const int bm = blockIdx.y * 128, bn = blockIdx.x * 128;

    const __nv_bfloat16* Bhi = Bhi1; const __nv_bfloat16* Blo = Blo1;
    const float* resid = resid1;
    float* C = C1;
    if (blockIdx.z == 1) { Bhi = Bhi2; Blo = Blo2; resid = resid2; C = C2; }

    float acc[2][8][4];
    #pragma unroll
    for (int mt = 0; mt < 2; mt++)
        #pragma unroll
        for (int nt = 0; nt < 8; nt++)
            #pragma unroll
            for (int r = 0; r < 4; r++) acc[mt][nt][r] = 0.f;

    GemmCtx cx;
    gemm_setup(cx, smraw, tid, Ahi, Alo, Bhi, Blo, bm, bn, K);
    gemm_mainloop(cx, acc, K);

    const int lane = tid & 31;
    const int grp = lane >> 2, qd = lane & 3;
    #pragma unroll
    for (int mt = 0; mt < 2; mt++) {
        int row0 = bm + cx.m0 + mt * 16 + grp;
        int row1 = row0 + 8;
        #pragma unroll
        for (int nt = 0; nt < 8; nt++) {
            int lc0 = cx.n0 + nt * 8 + 2 * qd;
            int col0 = bn + lc0, col1 = col0 + 1;
            float o00 = acc[mt][nt][0], o01 = acc[mt][nt][1];
            float o10 = acc[mt][nt][2], o11 = acc[mt][nt][3];
            if (resid) {
                o00 += resid[(size_t)row0 * N + col0];
                o01 += resid[(size_t)row0 * N + col1];
                o10 += resid[(size_t)row1 * N + col0];
                o11 += resid[(size_t)row1 * N + col1];
            }
            *(float2*)(C + (size_t)row0 * N + col0) = make_float2(o00, o01);
            *(float2*)(C + (size_t)row1 * N + col0) = make_float2(o10, o11);
        }
    }
}

// ---------------- attention scores on tensor cores: S = Qs * K^T (bf16x3) ----------------
__global__ __launch_bounds__(256, 2) void attn_scores_mma(
    const __nv_bfloat16* __restrict__ qh, const __nv_bfloat16* __restrict__ ql,
    const __nv_bfloat16* __restrict__ kh, const __nv_bfloat16* __restrict__ kl,
    float* __restrict__ scores) {
    if (blockIdx.x > blockIdx.y) return;
    extern __shared__ uint8_t smraw[];
    const int tid = threadIdx.x;
    const int bh = blockIdx.z;
    const int b = bh >> 4, hd = bh & 15, kvh = hd >> 2;
    const int bm = blockIdx.y * 128, bn = blockIdx.x * 128;
    float* C = scores + (size_t)bh * Sc * Sc;

    float acc[2][8][4];
    #pragma unroll
    for (int mt = 0; mt < 2; mt++)
        #pragma unroll
        for (int nt = 0; nt < 8; nt++)
            #pragma unroll
            for (int r = 0; r < 4; r++) acc[mt][nt][r] = 0.f;

    GemmCtx cx;
    {
        const int warpId = tid >> 5, lane = tid & 31;
        cx.m0 = (warpId & 3) * 32;
        cx.n0 = (warpId >> 2) * 64;
        cx.lrow16 = lane & 15;
        cx.lch = lane >> 4;
        cx.lsw = (cx.lrow16 >> 1) & 3;
        cx.sb = sptr(smraw);
        int lrow = tid >> 1;
        cx.lg0 = (tid & 1) * 2;
        cx.lswz = (lrow >> 1) & 3;
        cx.pAh = qh + (size_t)b * Sc * QNc + (size_t)hd * DHc + (size_t)(bm + lrow) * QNc;
        cx.pAl = ql + (size_t)b * Sc * QNc + (size_t)hd * DHc + (size_t)(bm + lrow) * QNc;
        cx.pBh = kh + (size_t)b * Sc * KNc + (size_t)kvh * DHc + (size_t)(bn + lrow) * KNc;
        cx.pBl = kl + (size_t)b * Sc * KNc + (size_t)kvh * DHc + (size_t)(bn + lrow) * KNc;
        cx.srow = cx.sb + lrow * 64;
    }
    gemm_mainloop(cx, acc, DHc);

    const int lane = tid & 31;
    const int grp = lane >> 2, qd = lane & 3;
    #pragma unroll
    for (int mt = 0; mt < 2; mt++) {
        int row0 = bm + cx.m0 + mt * 16 + grp;
        int row1 = row0 + 8;
        #pragma unroll
        for (int nt = 0; nt < 8; nt++) {
            int col = bn + cx.n0 + nt * 8 + 2 * qd;
            *(float2*)(C + (size_t)row0 * Sc + col) = make_float2(acc[mt][nt][0], acc[mt][nt][1]);
            *(float2*)(C + (size_t)row1 * Sc + col) = make_float2(acc[mt][nt][2], acc[mt][nt][3]);
        }
    }
}

// ---------------- attention context on tensor cores: ctx = P * V (bf16x3) ----------------
__global__ __launch_bounds__(256, 2) void attn_ctx_mma(
    const __nv_bfloat16* __restrict__ ph, const __nv_bfloat16* __restrict__ pl,
    const __nv_bfloat16* __restrict__ vTh, const __nv_bfloat16* __restrict__ vTl,
    __nv_bfloat16* __restrict__ ch, __nv_bfloat16* __restrict__ cl) {
    extern __shared__ uint8_t smraw[];
    const int tid = threadIdx.x;
    const int bh = blockIdx.z;
    const int b = bh >> 4, hd = bh & 15, kvh = hd >> 2;
    const int bm = blockIdx.y * 128;

    float acc[2][8][4];
    #pragma unroll
    for (int mt = 0; mt < 2; mt++)
        #pragma unroll
        for (int nt = 0; nt < 8; nt++)
            #pragma unroll
            for (int r = 0; r < 4; r++) acc[mt][nt][r] = 0.f;

    GemmCtx cx;
    {
        const int warpId = tid >> 5, lane = tid & 31;
        cx.m0 = (warpId & 3) * 32;
        cx.n0 = (warpId >> 2) * 64;
        cx.lrow16 = lane & 15;
        cx.lch = lane >> 4;
        cx.lsw = (cx.lrow16 >> 1) & 3;
        cx.sb = sptr(smraw);
        int lrow = tid >> 1;
        cx.lg0 = (tid & 1) * 2;
        cx.lswz = (lrow >> 1) & 3;
        cx.pAh = ph + (size_t)bh * Sc * Sc + (size_t)(bm + lrow) * Sc;
        cx.pAl = pl + (size_t)bh * Sc * Sc + (size_t)(bm + lrow) * Sc;
        cx.pBh = vTh + ((size_t)b * KNc + (size_t)kvh * DHc + lrow) * Sc;
        cx.pBl = vTl + ((size_t)b * KNc + (size_t)kvh * DHc + lrow) * Sc;
        cx.srow = cx.sb + lrow * 64;
    }
    gemm_mainloop(cx, acc, ((bm >> 5) + 4) << 5);   // causal truncation (exact)

    const int lane = tid & 31;
    const int grp = lane >> 2, qd = lane & 3;
    #pragma unroll
    for (int mt = 0; mt < 2; mt++) {
        int lr0 = cx.m0 + mt * 16 + grp;
        #pragma unroll
        for (int half = 0; half < 2; half++) {
            int row = bm + lr0 + half * 8;
            size_t base = ((size_t)(b * Sc + row)) * QNc + (size_t)hd * DHc;
            #pragma unroll
            for (int nt = 0; nt < 8; nt++) {
                int col = cx.n0 + nt * 8 + 2 * qd;
                float v0 = acc[mt][nt][half * 2 + 0];
                float v1 = acc[mt][nt][half * 2 + 1];
                __nv_bfloat16 h0 = __float2bfloat16(v0);
                __nv_bfloat16 h1 = __float2bfloat16(v1);
                __nv_bfloat162 hv; hv.x = h0; hv.y = h1;
                __nv_bfloat162 lv;
                lv.x = __float2bfloat16(v0 - __bfloat162float(h0));
                lv.y = __float2bfloat16(v1 - __bfloat162float(h1));
                *(__nv_bfloat162*)(ch + base + col) = hv;
                *(__nv_bfloat162*)(cl + base + col) = lv;
            }
        }
    }
}

// ---------------- RoPE (q+k fused), table-driven, + scale + bf16 hi/lo split ----------------
// block (64,4): 4 head-slices per 256-thread block; grid (MTc, 5) covers 20 heads.
__global__ void rope_split2_kernel(const float* __restrict__ qb, const float* __restrict__ kb,
                                   const float* __restrict__ rc, const float* __restrict__ rs,
                                   __nv_bfloat16* __restrict__ qh, __nv_bfloat16* __restrict__ ql,
                                   __nv_bfloat16* __restrict__ kh, __nv_bfloat16* __restrict__ kl) {
    int token = blockIdx.x;
    int head  = blockIdx.y * 4 + threadIdx.y;   // 0..19: 0-15 = q, 16-19 = k
    int d = threadIdx.x;
    int s = token % Sc;
    const float* p;
    __nv_bfloat16 *oh, *ol;
    size_t idx;
    float scale;
    if (head < NHc) {
        p = qb + ((size_t)token * NHc + head) * DHc;
        idx = ((size_t)token * NHc + head) * DHc;
        oh = qh; ol = ql; scale = INV_SQRT_DH;
    } else {
        int h2 = head - NHc;
        p = kb + ((size_t)token * NKVc + h2) * DHc;
        idx = ((size_t)token * NKVc + h2) * DHc;
        oh = kh; ol = kl; scale = 1.0f;
    }
    float cs = rc[s * 64 + d];
    float sn = rs[s * 64 + d];
    float x1 = p[d], x2 = p[d + 64];
    float v0 = (x1 * cs - x2 * sn) * scale;
    float v1 = (x2 * cs + x1 * sn) * scale;
    __nv_bfloat16 h0 = __float2bfloat16(v0);
    __nv_bfloat16 h1 = __float2bfloat16(v1);
    oh[idx + d]      = h0;
    ol[idx + d]      = __float2bfloat16(v0 - __bfloat162float(h0));
    oh[idx + d + 64] = h1;
    ol[idx + d + 64] = __float2bfloat16(v1 - __bfloat162float(h1));
}

// ---------------- V transpose + split ----------------
__global__ void vsplitT_kernel(const float* __restrict__ v,
                               __nv_bfloat16* __restrict__ vTh,
                               __nv_bfloat16* __restrict__ vTl) {
    __shared__ float tile[32][33];
    int b = blockIdx.z;
    int t0 = blockIdx.x * 32, d0 = blockIdx.y * 32;
    int tx = threadIdx.x, ty = threadIdx.y;
    for (int i = ty; i < 32; i += 8)
        tile[i][tx] = v[(size_t)(b * Sc + t0 + i) * KNc + d0 + tx];
    __syncthreads();
    for (int i = ty; i < 32; i += 8) {
        float val = tile[tx][i];
        size_t idx = ((size_t)b * KNc + d0 + i) * Sc + t0 + tx;
        __nv_bfloat16 hb = __float2bfloat16(val);
        vTh[idx] = hb;
        vTl[idx] = __float2bfloat16(val - __bfloat162float(hb));
    }
}

// ---------------- masked softmax -> bf16 hi/lo P ----------------
__global__ void softmax_kernel(const float* __restrict__ scores, const int* __restrict__ mask,
                               __nv_bfloat16* __restrict__ ph, __nv_bfloat16* __restrict__ pl) {
    int row = blockIdx.x;
    int qpos = row % Sc;
    int b = row / (NHc * Sc);
    const float* r = scores + (size_t)row * Sc;
    int t = threadIdx.x;
    float v[4];
    float mx = -3.0e38f;
    #pragma unroll
    for (int i = 0; i < 4; i++) {
        int k = t + 128 * i;
        bool ok = (k <= qpos) && (mask[b * Sc + k] > 0);
        v[i] = ok ? r[k] : -1e30f;
        mx = fmaxf(mx, v[i]);
    }
    __shared__ float sh[128];
    sh[t] = mx; __syncthreads();
    for (int o = 64; o; o >>= 1) { if (t < o) sh[t] = fmaxf(sh[t], sh[t + o]); __syncthreads(); }
    mx = sh[0]; __syncthreads();
    float sm = 0.f;
    #pragma unroll
    for (int i = 0; i < 4; i++) { v[i] = expf(v[i] - mx); sm += v[i]; }
    sh[t] = sm; __syncthreads();
    for (int o = 64; o; o >>= 1) { if (t < o) sh[t] += sh[t + o]; __syncthreads(); }
    float inv = 1.0f / sh[0];
    #pragma unroll
    for (int i = 0; i < 4; i++) {
        float p = v[i] * inv;
        __nv_bfloat16 hb = __float2bfloat16(p);
        ph[(size_t)row * Sc + t + 128 * i] = hb;
        pl[(size_t)row * Sc + t + 128 * i] = __float2bfloat16(p - __bfloat162float(hb));
    }
}

// ---------------- silu(g)*u -> bf16 hi/lo ----------------
__global__ void silu_mul_kernel(const float* __restrict__ g, const float* __restrict__ u,
                                __nv_bfloat16* __restrict__ gh, __nv_bfloat16* __restrict__ gl, int n) {
    int i = blockIdx.x * 256 + threadIdx.x;
    if (i < n) {
        float x = g[i];
        float v = (x / (1.0f + expf(-x))) * u[i];
        __nv_bfloat16 hb = __float2bfloat16(v);
        gh[i] = hb;
        gl[i] = __float2bfloat16(v - __bfloat162float(hb));
    }
}

// ---------------- final pooling + rmsnorm(lnf) ----------------
__global__ void pool_kernel(const float* __restrict__ h, const int* __restrict__ mask,
                            const float* __restrict__ lnf, float* __restrict__ pooled) {
    int b = blockIdx.x;
    int t = threadIdx.x;
    __shared__ float sh[256];
    int cnt = 0;
    for (int i = t; i < Sc; i += 256) cnt += mask[b * Sc + i];
    sh[t] = (float)cnt; __syncthreads();
    for (int o = 128; o; o >>= 1) { if (t < o) sh[t] += sh[t + o]; __syncthreads(); }
    int last = (int)sh[0] - 1;
    __syncthreads();
    const float* row = h + ((size_t)b * Sc + last) * Hc;
    float ss = 0.f;
    for (int i = t; i < Hc; i += 256) { float x = row[i]; ss += x * x; }
    sh[t] = ss; __syncthreads();
    for (int o = 128; o; o >>= 1) { if (t < o) sh[t] += sh[t + o]; __syncthreads(); }
    float sc = rsqrtf(sh[0] / (float)Hc + 1e-6f);
    for (int i = t; i < Hc; i += 256) pooled[b * Hc + i] = row[i] * sc * lnf[i];
}

// ---------------- classifier ----------------
__global__ void cls1_kernel(const float* __restrict__ pooled, const float* __restrict__ cw1,
                            const float* __restrict__ cb1, float* __restrict__ hid) {
    int n = blockIdx.x * 128 + threadIdx.x;
    int b = blockIdx.y;
    float acc = cb1[n];
    const float* p = pooled + (size_t)b * Hc;
    for (int k = 0; k < Hc; k++) acc += p[k] * cw1[(size_t)k * Hc + n];
    hid[(size_t)b * Hc + n] = fmaxf(acc, 0.f);
}

__global__ void cls2_kernel(const float* __restrict__ hid, const float* __restrict__ cw2,
                            const float* __restrict__ cb2, float* __restrict__ out) {
    int b = blockIdx.x >> 1, c = blockIdx.x & 1;
    float acc = 0.f;
    for (int k = threadIdx.x; k < Hc; k += 128) acc += hid[(size_t)b * Hc + k] * cw2[k * NCc + c];
    __shared__ float sh[128];
    sh[threadIdx.x] = acc; __syncthreads();
    for (int o = 64; o; o >>= 1) { if (threadIdx.x < o) sh[threadIdx.x] += sh[threadIdx.x + o]; __syncthreads(); }
    if (threadIdx.x == 0) out[b * NCc + c] = sh[0] + cb2[c];
}

// ---------------- host orchestration ----------------
extern "C" void kernel_launch(void* const* d_in, const int* in_sizes, int n_in,
                              void* d_out, int out_size) {
    (void)in_sizes; (void)n_in; (void)out_size;
    const int*   ids   = (const int*)d_in[0];
    const int*   mask  = (const int*)d_in[1];
    const float* embed = (const float*)d_in[2];
    const float* ln1   = (const float*)d_in[3];
    const float* wq    = (const float*)d_in[4];
    const float* bq    = (const float*)d_in[5];
    const float* wk    = (const float*)d_in[6];
    const float* bk    = (const float*)d_in[7];
    const float* wv    = (const float*)d_in[8];
    const float* bv    = (const float*)d_in[9];
    const float* wo    = (const float*)d_in[10];
    const float* laq   = (const float*)d_in[11];
    const float* lbq   = (const float*)d_in[12];
    const float* lak   = (const float*)d_in[13];
    const float* lbk   = (const float*)d_in[14];
    const float* lav   = (const float*)d_in[15];
    const float* lbv   = (const float*)d_in[16];
    const float* lao   = (const float*)d_in[17];
    const float* lbo   = (const float*)d_in[18];
    const float* ln2   = (const float*)d_in[19];
    const float* wg    = (const float*)d_in[20];
    const float* wu    = (const float*)d_in[21];
    const float* wd    = (const float*)d_in[22];
    const float* lnf   = (const float*)d_in[23];
    const float* cw1   = (const float*)d_in[24];
    const float* cb1   = (const float*)d_in[25];
    const float* cw2   = (const float*)d_in[26];
    const float* cb2   = (const float*)d_in[27];
    float* out = (float*)d_out;

    cudaFuncSetAttribute(gemm_qkv, cudaFuncAttributeMaxDynamicSharedMemorySize, GEMM_SMEM);
    cudaFuncSetAttribute(gemm_bf16x3, cudaFuncAttributeMaxDynamicSharedMemorySize, GEMM_SMEM);
    cudaFuncSetAttribute(attn_scores_mma, cudaFuncAttributeMaxDynamicSharedMemorySize, GEMM_SMEM);
    cudaFuncSetAttribute(attn_ctx_mma, cudaFuncAttributeMaxDynamicSharedMemorySize, GEMM_SMEM);

    float *h, *q, *k, *v, *sc, *g, *u, *pooled, *cls, *rc, *rs;
    __nv_bfloat16 *xh, *xl, *qh, *ql, *kh, *kl, *vTh, *vTl, *ph, *pl, *ch, *cl, *gh, *gl, *whT, *wlT;
    cudaGetSymbolAddress((void**)&h,   d_h);
    cudaGetSymbolAddress((void**)&xh,  d_xh);
    cudaGetSymbolAddress((void**)&xl,  d_xl);
    cudaGetSymbolAddress((void**)&q,   d_q);
    cudaGetSymbolAddress((void**)&k,   d_k);
    cudaGetSymbolAddress((void**)&v,   d_v);
    cudaGetSymbolAddress((void**)&qh,  d_qh);
    cudaGetSymbolAddress((void**)&ql,  d_ql);
    cudaGetSymbolAddress((void**)&kh,  d_kh);
    cudaGetSymbolAddress((void**)&kl,  d_kl);
    cudaGetSymbolAddress((void**)&vTh, d_vTh);
    cudaGetSymbolAddress((void**)&vTl, d_vTl);
    cudaGetSymbolAddress((void**)&rc,  d_ropec);
    cudaGetSymbolAddress((void**)&rs,  d_ropes);
    cudaGetSymbolAddress((void**)&sc,  d_sc);
    cudaGetSymbolAddress((void**)&ph,  d_ph);
    cudaGetSymbolAddress((void**)&pl,  d_pl);
    cudaGetSymbolAddress((void**)&ch,  d_ch);
    cudaGetSymbolAddress((void**)&cl,  d_cl);
    cudaGetSymbolAddress((void**)&g,   d_g);
    cudaGetSymbolAddress((void**)&u,   d_u);
    cudaGetSymbolAddress((void**)&gh,  d_gh);
    cudaGetSymbolAddress((void**)&gl,  d_gl);
    cudaGetSymbolAddress((void**)&pooled, d_pooled);
    cudaGetSymbolAddress((void**)&cls,    d_cls);
    cudaGetSymbolAddress((void**)&whT,    d_whT);
    cudaGetSymbolAddress((void**)&wlT,    d_wlT);

    wsplit_all_kernel<<<Lc * TILES_PER_LAYER, dim3(32, 8)>>>(
        wq, wk, wv, wo, wg, wu, wd,
        laq, lbq, lak, lbk, lav, lbv, lao, lbo, whT, wlT);
    embed_kernel<<<MTc, 256>>>(ids, embed, h);

    for (int l = 0; l < Lc; l++) {
        size_t lw = (size_t)l * LAYER_W;
        const float* LN1 = ln1 + (size_t)l * Hc;
        const float* BQ = bq + (size_t)l * QNc;
        const float* BK = bk + (size_t)l * KNc;
        const float* BV = bv + (size_t)l * KNc;
        const float* LN2 = ln2 + (size_t)l * Hc;

        rmsnorm_kernel<<<MTc, 256>>>(h, LN1, xh, xl);

        // fused QKV projection: 24 N-tiles x 16 M-tiles = 384 CTAs
        gemm_qkv<<<dim3(24, MTc / 128), 256, GEMM_SMEM>>>(
            xh, xl,
            whT + lw + WOFF_Q, wlT + lw + WOFF_Q,
            whT + lw + WOFF_K, wlT + lw + WOFF_K,
            whT + lw + WOFF_V, wlT + lw + WOFF_V,
            BQ, BK, BV, q, k, v);

        if (l == 0) rope_table_kernel<<<Sc, 64>>>(rc, rs);

        rope_split2_kernel<<<dim3(MTc, 5), dim3(64, 4)>>>(q, k, rc, rs, qh, ql, kh, kl);
        vsplitT_kernel<<<dim3(16, 16, Bc), dim3(32, 8)>>>(v, vTh, vTl);

        attn_scores_mma<<<dim3(4, 4, Bc * NHc), 256, GEMM_SMEM>>>(qh, ql, kh, kl, sc);
        softmax_kernel<<<Bc * NHc * Sc, 128>>>(sc, mask, ph, pl);
        attn_ctx_mma<<<dim3(1, 4, Bc * NHc), 256, GEMM_SMEM>>>(ph, pl, vTh, vTl, ch, cl);

        gemm_bf16x3<<<dim3(Hc / 128, MTc / 128, 1), 256, GEMM_SMEM>>>(
            ch, cl,
            whT + lw + WOFF_O, wlT + lw + WOFF_O, h, h,
            nullptr, nullptr, nullptr, nullptr,
            MTc, Hc, QNc);

        rmsnorm_kernel<<<MTc, 256>>>(h, LN2, xh, xl);
        gemm_bf16x3<<<dim3(Fc / 128, MTc / 128, 2), 256, GEMM_SMEM>>>(
            xh, xl,
            whT + lw + WOFF_G, wlT + lw + WOFF_G, nullptr, g,
            whT + lw + WOFF_U, wlT + lw + WOFF_U, nullptr, u,
            MTc, Fc, Hc);
        silu_mul_kernel<<<(MTc * Fc) / 256, 256>>>(g, u, gh, gl, MTc * Fc);
        gemm_bf16x3<<<dim3(Hc / 128, MTc / 128, 1), 256, GEMM_SMEM>>>(
            gh, gl,
            whT + lw + WOFF_D, wlT + lw + WOFF_D, h, h,
            nullptr, nullptr, nullptr, nullptr,
            MTc, Hc, Fc);
    }

    pool_kernel<<<Bc, 256>>>(h, mask, lnf, pooled);
    cls1_kernel<<<dim3(Hc / 128, Bc), 128>>>(pooled, cw1, cb1, cls);
    cls2_kernel<<<Bc * NCc, 128>>>(cls, cw2, cb2, out);
}

// round 17
// speedup vs baseline: 2.0554x; 1.0044x over previous
#include <cuda_runtime.h>
#include <cuda_bf16.h>
#include <cstddef>
#include <cstdint>
#include <math.h>

// ---------------- problem constants ----------------
#define Lc   4
#define Hc   2048
#define NHc  16
#define NKVc 4
#define DHc  128
#define Fc   5632
#define Rc   16
#define Bc   4
#define Sc   512
#define NCc  2
#define MTc  (Bc * Sc)          // 2048 tokens
#define QNc  (NHc * DHc)        // 2048
#define KNc  (NKVc * DHc)       // 512
#define LORA_SCALE 2.0f
#define INV_SQRT_DH 0.08838834764831845f

// per-layer transposed weight buffer offsets (elements)
#define WOFF_Q 0
#define WOFF_K (WOFF_Q + Hc * QNc)
#define WOFF_V (WOFF_K + Hc * KNc)
#define WOFF_O (WOFF_V + Hc * KNc)
#define WOFF_G (WOFF_O + QNc * Hc)
#define WOFF_U (WOFF_G + Hc * Fc)
#define WOFF_D (WOFF_U + Hc * Fc)
#define LAYER_W (WOFF_D + Fc * Hc)   // 45,088,768

// ---------------- scratch (static device memory; allocation-free) ----------------
__device__ float          d_h[MTc * Hc];
__device__ __nv_bfloat16  d_xh[MTc * Hc];
__device__ __nv_bfloat16  d_xl[MTc * Hc];
__device__ float          d_v[MTc * KNc];
__device__ __nv_bfloat16  d_qh[MTc * QNc];
__device__ __nv_bfloat16  d_ql[MTc * QNc];
__device__ __nv_bfloat16  d_kh[MTc * KNc];
__device__ __nv_bfloat16  d_kl[MTc * KNc];
__device__ __nv_bfloat16  d_vTh[Bc * KNc * Sc];
__device__ __nv_bfloat16  d_vTl[Bc * KNc * Sc];
__device__ float          d_ropec[Sc * 64];
__device__ float          d_ropes[Sc * 64];
__device__ float          d_sc[Bc * NHc * Sc * Sc];
__device__ __nv_bfloat16  d_ph[Bc * NHc * Sc * Sc];
__device__ __nv_bfloat16  d_pl[Bc * NHc * Sc * Sc];
__device__ __nv_bfloat16  d_ch[MTc * QNc];
__device__ __nv_bfloat16  d_cl[MTc * QNc];
__device__ float          d_g[MTc * Fc];
__device__ float          d_u[MTc * Fc];
__device__ __nv_bfloat16  d_gh[MTc * Fc];
__device__ __nv_bfloat16  d_gl[MTc * Fc];
__device__ float          d_pooled[Bc * Hc];
__device__ float          d_cls[Bc * Hc];
__device__ __nv_bfloat16  d_whT[(size_t)Lc * LAYER_W];  // hi weights (lora folded), [N,K]
__device__ __nv_bfloat16  d_wlT[(size_t)Lc * LAYER_W];  // lo weights, [N,K]

// ---------------- PTX helpers ----------------
__device__ __forceinline__ uint32_t sptr(const void* p) {
    return (uint32_t)__cvta_generic_to_shared(p);
}
#define CP_ASYNC16(dst, src) asm volatile("cp.async.cg.shared.global [%0], [%1], 16;\n" :: "r"(dst), "l"(src))
#define CP_COMMIT()          asm volatile("cp.async.commit_group;\n" ::: "memory")
#define CP_WAIT(n)           asm volatile("cp.async.wait_group %0;\n" :: "n"(n) : "memory")

__device__ __forceinline__ void mma_bf16(float* c, const uint32_t* a, const uint32_t* b) {
    asm volatile(
        "mma.sync.aligned.m16n8k16.row.col.f32.bf16.bf16.f32 "
        "{%0,%1,%2,%3}, {%4,%5,%6,%7}, {%8,%9}, {%0,%1,%2,%3};\n"
        : "+f"(c[0]), "+f"(c[1]), "+f"(c[2]), "+f"(c[3])
        : "r"(a[0]), "r"(a[1]), "r"(a[2]), "r"(a[3]), "r"(b[0]), "r"(b[1]));
}

__device__ __forceinline__ void ldsm4(uint32_t* r, uint32_t addr) {
    asm volatile("ldmatrix.sync.aligned.m8n8.x4.shared.b16 {%0,%1,%2,%3}, [%4];"
        : "=r"(r[0]), "=r"(r[1]), "=r"(r[2]), "=r"(r[3]) : "r"(addr));
}

// ---------------- ALL weights: transpose + LoRA fold + bf16 split, ONE launch ----------------
#define TILES_PER_LAYER 22016
__global__ void wsplit_all_kernel(const float* __restrict__ wq, const float* __restrict__ wk,
                                  const float* __restrict__ wv, const float* __restrict__ wo,
                                  const float* __restrict__ wg, const float* __restrict__ wu,
                                  const float* __restrict__ wd,
                                  const float* __restrict__ laq, const float* __restrict__ lbq,
                                  const float* __restrict__ lak, const float* __restrict__ lbk,
                                  const float* __restrict__ lav, const float* __restrict__ lbv,
                                  const float* __restrict__ lao, const float* __restrict__ lbo,
                                  __nv_bfloat16* __restrict__ hiT,
                                  __nv_bfloat16* __restrict__ loT) {
    int l = blockIdx.x / TILES_PER_LAYER;
    int r = blockIdx.x % TILES_PER_LAYER;
    const float* src; size_t woff; int K, N, tidx;
    const float* loA = nullptr; const float* loB = nullptr;
    if (r < 2048)       { src = wq + (size_t)l * Hc * QNc; woff = WOFF_Q; K = Hc;  N = QNc; tidx = r;
                          loA = laq + (size_t)l * Rc * Hc;  loB = lbq + (size_t)l * QNc * Rc; }
    else if (r < 2560)  { src = wk + (size_t)l * Hc * KNc; woff = WOFF_K; K = Hc;  N = KNc; tidx = r - 2048;
                          loA = lak + (size_t)l * Rc * Hc;  loB = lbk + (size_t)l * KNc * Rc; }
    else if (r < 3072)  { src = wv + (size_t)l * Hc * KNc; woff = WOFF_V; K = Hc;  N = KNc; tidx = r - 2560;
                          loA = lav + (size_t)l * Rc * Hc;  loB = lbv + (size_t)l * KNc * Rc; }
    else if (r < 5120)  { src = wo + (size_t)l * QNc * Hc; woff = WOFF_O; K = QNc; N = Hc;  tidx = r - 3072;
                          loA = lao + (size_t)l * Rc * QNc; loB = lbo + (size_t)l * Hc * Rc; }
    else if (r < 10752) { src = wg + (size_t)l * Hc * Fc;  woff = WOFF_G; K = Hc;  N = Fc;  tidx = r - 5120; }
    else if (r < 16384) { src = wu + (size_t)l * Hc * Fc;  woff = WOFF_U; K = Hc;  N = Fc;  tidx = r - 10752; }
    else                { src = wd + (size_t)l * Fc * Hc;  woff = WOFF_D; K = Fc;  N = Hc;  tidx = r - 16384; }
    woff += (size_t)l * LAYER_W;
    int nt = N / 32;
    int k0 = (tidx / nt) * 64, n0 = (tidx % nt) * 32;

    __shared__ float tile[64][33];   // [k][n]
    __shared__ float sA[16][64];     // lora A[r][k-local]
    __shared__ float sB[32][17];     // lora B[n-local][r]
    int tx = threadIdx.x, ty = threadIdx.y;   // (32, 8)
    int tid = ty * 32 + tx;
    for (int i = ty; i < 64; i += 8)
        tile[i][tx] = src[(size_t)(k0 + i) * N + n0 + tx];
    if (loA) {
        for (int idx = tid; idx < 1024; idx += 256) {
            int rr = idx >> 6, kk = idx & 63;
            sA[rr][kk] = loA[(size_t)rr * K + k0 + kk];
        }
        for (int idx = tid; idx < 512; idx += 256) {
            int nn = idx >> 4, rr = idx & 15;
            sB[nn][rr] = loB[(size_t)(n0 + nn) * Rc + rr];
        }
    }
    __syncthreads();
    for (int i = ty; i < 32; i += 8) {
        float v0 = tile[2 * tx][i], v1 = tile[2 * tx + 1][i];
        if (loA) {
            float d0 = 0.f, d1 = 0.f;
            #pragma unroll
            for (int rr = 0; rr < Rc; rr++) {
                float bb = sB[i][rr];
                d0 += sA[rr][2 * tx] * bb;
                d1 += sA[rr][2 * tx + 1] * bb;
            }
            v0 += LORA_SCALE * d0;
            v1 += LORA_SCALE * d1;
        }
        __nv_bfloat16 h0 = __float2bfloat16(v0), h1 = __float2bfloat16(v1);
        __nv_bfloat162 hv; hv.x = h0; hv.y = h1;
        __nv_bfloat162 lv;
        lv.x = __float2bfloat16(v0 - __bfloat162float(h0));
        lv.y = __float2bfloat16(v1 - __bfloat162float(h1));
        size_t idx = woff + (size_t)(n0 + i) * K + k0 + 2 * tx;
        *(__nv_bfloat162*)(hiT + idx) = hv;
        *(__nv_bfloat162*)(loT + idx) = lv;
    }
}

// ---------------- RoPE table precompute ----------------
__global__ void rope_table_kernel(float* __restrict__ rc, float* __restrict__ rs) {
    int s = blockIdx.x;
    int d = threadIdx.x;
    float freq = powf(1000000.0f, -(float)d / 64.0f);
    float ang = (float)s * freq;
    float sn, cs;
    sincosf(ang, &sn, &cs);
    rc[s * 64 + d] = cs;
    rs[s * 64 + d] = sn;
}

// ---------------- embedding gather ----------------
__global__ void embed_kernel(const int* __restrict__ ids,
                             const float* __restrict__ emb,
                             float* __restrict__ h) {
    int row = blockIdx.x;
    const float* src = emb + (size_t)ids[row] * Hc;
    float* dst = h + (size_t)row * Hc;
    for (int i = threadIdx.x; i < Hc; i += 256) dst[i] = src[i];
}

// ---------------- rmsnorm: bf16 hi/lo split only ----------------
__global__ void rmsnorm_kernel(const float* __restrict__ in,
                               const float* __restrict__ w,
                               __nv_bfloat16* __restrict__ oh,
                               __nv_bfloat16* __restrict__ ol) {
    int row = blockIdx.x;
    const float* x = in + (size_t)row * Hc;
    float ss = 0.f;
    for (int i = threadIdx.x; i < Hc; i += 256) { float v = x[i]; ss += v * v; }
    __shared__ float sh[256];
    sh[threadIdx.x] = ss; __syncthreads();
    for (int o = 128; o; o >>= 1) { if (threadIdx.x < o) sh[threadIdx.x] += sh[threadIdx.x + o]; __syncthreads(); }
    float sc = rsqrtf(sh[0] / (float)Hc + 1e-6f);
    for (int i = threadIdx.x; i < Hc; i += 256) {
        float v = x[i] * sc * w[i];
        __nv_bfloat16 hb = __float2bfloat16(v);
        oh[(size_t)row * Hc + i] = hb;
        ol[(size_t)row * Hc + i] = __float2bfloat16(v - __bfloat162float(hb));
    }
}

// ================= shared GEMM mainloop =================
#define TILE_B 8192                  // 128 * 64B
#define STAGE_B (4 * TILE_B)         // Ah, Al, Bh, Bl = 32KB
#define NSTAGE 3
#define GEMM_SMEM (NSTAGE * STAGE_B) // 96KB

struct GemmCtx {
    const __nv_bfloat16 *pAh, *pAl, *pBh, *pBl;
    uint32_t sb, srow;
    int lg0, lswz;
    int m0, n0, lrow16, lch, lsw;
};

__device__ __forceinline__ void gemm_mainloop(GemmCtx& cx, float acc[2][8][4], int K) {
    auto loadStage = [&](int st, int k0) {
        uint32_t d = cx.srow + st * STAGE_B;
        #pragma unroll
        for (int i = 0; i < 2; i++) {
            int g = cx.lg0 + i;
            uint32_t off = (uint32_t)(g ^ cx.lswz) << 4;
            CP_ASYNC16(d + 0 * TILE_B + off, cx.pAh + k0 + g * 8);
            CP_ASYNC16(d + 1 * TILE_B + off, cx.pAl + k0 + g * 8);
            CP_ASYNC16(d + 2 * TILE_B + off, cx.pBh + k0 + g * 8);
            CP_ASYNC16(d + 3 * TILE_B + off, cx.pBl + k0 + g * 8);
        }
        CP_COMMIT();
    };
    const int KT = K >> 5;
    loadStage(0, 0);
    if (KT > 1) loadStage(1, 32);

    for (int kt = 0; kt < KT; kt++) {
        const int st = kt % NSTAGE;
        if (kt + 1 < KT) { CP_WAIT(1); } else { CP_WAIT(0); }
        __syncthreads();
        if (kt + 2 < KT) loadStage((kt + 2) % NSTAGE, (kt + 2) << 5);

        const uint32_t tAh = cx.sb + st * STAGE_B;
        const uint32_t tAl = tAh + TILE_B;
        const uint32_t tBh = tAh + 2 * TILE_B;
        const uint32_t tBl = tAh + 3 * TILE_B;

        #pragma unroll
        for (int ks = 0; ks < 2; ks++) {
            const uint32_t choff = (uint32_t)(((ks * 2 + cx.lch) ^ cx.lsw)) << 4;
            uint32_t ra0 = (uint32_t)(cx.m0 + cx.lrow16) * 64 + choff;
            uint32_t ra1 = (uint32_t)(cx.m0 + 16 + cx.lrow16) * 64 + choff;
            uint32_t rb0 = (uint32_t)(cx.n0 + cx.lrow16) * 64 + choff;

            uint32_t afH[2][4], afL[2][4], bf[8][2];
            #pragma unroll
            for (int np = 0; np < 4; np++) {
                uint32_t q[4];
                ldsm4(q, tBh + rb0 + (uint32_t)(np * 16 * 64));
                bf[2 * np][0] = q[0]; bf[2 * np + 1][0] = q[1];
                bf[2 * np][1] = q[2]; bf[2 * np + 1][1] = q[3];
            }
            ldsm4(afH[0], tAh + ra0);
            ldsm4(afH[1], tAh + ra1);
            #pragma unroll
            for (int mt = 0; mt < 2; mt++)
                #pragma unroll
                for (int nt = 0; nt < 8; nt++)
                    mma_bf16(acc[mt][nt], afH[mt], bf[nt]);
            ldsm4(afL[0], tAl + ra0);
            ldsm4(afL[1], tAl + ra1);
            #pragma unroll
            for (int mt = 0; mt < 2; mt++)
                #pragma unroll
                for (int nt = 0; nt < 8; nt++)
                    mma_bf16(acc[mt][nt], afL[mt], bf[nt]);
            #pragma unroll
            for (int np = 0; np < 4; np++) {
                uint32_t q[4];
                ldsm4(q, tBl + rb0 + (uint32_t)(np * 16 * 64));
                bf[2 * np][0] = q[0]; bf[2 * np + 1][0] = q[1];
                bf[2 * np][1] = q[2]; bf[2 * np + 1][1] = q[3];
            }
            #pragma unroll
            for (int mt = 0; mt < 2; mt++)
                #pragma unroll
                for (int nt = 0; nt < 8; nt++)
                    mma_bf16(acc[mt][nt], afH[mt], bf[nt]);
        }
    }
}

__device__ __forceinline__ void gemm_setup(GemmCtx& cx, uint8_t* smraw, int tid,
                                           const __nv_bfloat16* Ahi, const __nv_bfloat16* Alo,
                                           const __nv_bfloat16* Bhi, const __nv_bfloat16* Blo,
                                           int bm, int bn, int K) {
    const int warpId = tid >> 5, lane = tid & 31;
    cx.m0 = (warpId & 3) * 32;
    cx.n0 = (warpId >> 2) * 64;
    cx.lrow16 = lane & 15;
    cx.lch = lane >> 4;
    cx.lsw = (cx.lrow16 >> 1) & 3;
    cx.sb = sptr(smraw);
    int lrow = tid >> 1;
    cx.lg0 = (tid & 1) * 2;
    cx.lswz = (lrow >> 1) & 3;
    cx.pAh = Ahi + (size_t)(bm + lrow) * K;
    cx.pAl = Alo + (size_t)(bm + lrow) * K;
    cx.pBh = Bhi + (size_t)(bn + lrow) * K;
    cx.pBl = Blo + (size_t)(bn + lrow) * K;
    cx.srow = cx.sb + lrow * 64;
}

// ---------------- fused QKV GEMM + RoPE epilogue ----------------
// 24 N-tiles (16 Q + 4 K + 4 V) x 16 M-tiles. Q/K tiles: stage fp32 tile in smem,
// apply rope+scale+bf16 split inline (outputs bit-identical to the old rope kernel).
__global__ __launch_bounds__(256, 2) void gemm_qkv(
    const __nv_bfloat16* __restrict__ Ahi, const __nv_bfloat16* __restrict__ Alo,
    const __nv_bfloat16* __restrict__ WQh, const __nv_bfloat16* __restrict__ WQl,
    const __nv_bfloat16* __restrict__ WKh, const __nv_bfloat16* __restrict__ WKl,
    const __nv_bfloat16* __restrict__ WVh, const __nv_bfloat16* __restrict__ WVl,
    const float* __restrict__ BQ, const float* __restrict__ BK, const float* __restrict__ BV,
    const float* __restrict__ rc, const float* __restrict__ rs,
    __nv_bfloat16* __restrict__ qh, __nv_bfloat16* __restrict__ ql,
    __nv_bfloat16* __restrict__ kh, __nv_bfloat16* __restrict__ kl,
    float* __restrict__ v) {
    extern __shared__ uint8_t smraw[];
    const int tid = threadIdx.x;
    const int bx = blockIdx.x;
    const int bm = blockIdx.y * 128;

    const __nv_bfloat16 *Bhi, *Blo;
    const float* bias;
    int ntile;
    if (bx < 16)      { Bhi = WQh; Blo = WQl; bias = BQ; ntile = bx; }
    else if (bx < 20) { Bhi = WKh; Blo = WKl; bias = BK; ntile = bx - 16; }
    else              { Bhi = WVh; Blo = WVl; bias = BV; ntile = bx - 20; }
    const int bn = ntile * 128;

    float acc[2][8][4];
    #pragma unroll
    for (int mt = 0; mt < 2; mt++)
        #pragma unroll
        for (int nt = 0; nt < 8; nt++)
            #pragma unroll
            for (int r = 0; r < 4; r++) acc[mt][nt][r] = 0.f;

    GemmCtx cx;
    gemm_setup(cx, smraw, tid, Ahi, Alo, Bhi, Blo, bm, bn, Hc);
    gemm_mainloop(cx, acc, Hc);

    const int lane = tid & 31;
    const int grp = lane >> 2, qd = lane & 3;

    if (bx >= 20) {
        // V tile: plain fp32 store (+bias)
        #pragma unroll
        for (int mt = 0; mt < 2; mt++) {
            int row0 = bm + cx.m0 + mt * 16 + grp;
            int row1 = row0 + 8;
            #pragma unroll
            for (int nt = 0; nt < 8; nt++) {
                int lc0 = cx.n0 + nt * 8 + 2 * qd;
                int col0 = bn + lc0, col1 = col0 + 1;
                float b0 = bias[col0], b1 = bias[col1];
                *(float2*)(v + (size_t)row0 * KNc + col0) =
                    make_float2(acc[mt][nt][0] + b0, acc[mt][nt][1] + b1);
                *(float2*)(v + (size_t)row1 * KNc + col0) =
                    make_float2(acc[mt][nt][2] + b0, acc[mt][nt][3] + b1);
            }
        }
        return;
    }

    // Q/K tile: stage fp32 (acc+bias) in smem, then rope + split.
    float* so = (float*)smraw;   // [128][132] fp32 = 67584 B
    __syncthreads();             // mainloop smem fully consumed by all warps
    #pragma unroll
    for (int mt = 0; mt < 2; mt++) {
        int lr0 = cx.m0 + mt * 16 + grp;
        int lr1 = lr0 + 8;
        #pragma unroll
        for (int nt = 0; nt < 8; nt++) {
            int lc0 = cx.n0 + nt * 8 + 2 * qd;
            float b0 = bias[bn + lc0], b1 = bias[bn + lc0 + 1];
            so[lr0 * 132 + lc0]     = acc[mt][nt][0] + b0;
            so[lr0 * 132 + lc0 + 1] = acc[mt][nt][1] + b1;
            so[lr1 * 132 + lc0]     = acc[mt][nt][2] + b0;
            so[lr1 * 132 + lc0 + 1] = acc[mt][nt][3] + b1;
        }
    }
    __syncthreads();

    const bool isQ = (bx < 16);
    __nv_bfloat16* oh = isQ ? qh : kh;
    __nv_bfloat16* ol = isQ ? ql : kl;
    const float scale = isQ ? INV_SQRT_DH : 1.0f;
    const int nheads = isQ ? NHc : NKVc;
    const int head = ntile;
    const int d = tid & 63;
    const int rg = tid >> 6;     // 4 row groups
    for (int r = rg; r < 128; r += 4) {
        int token = bm + r;
        int s = token & (Sc - 1);
        float cs = rc[s * 64 + d];
        float sn = rs[s * 64 + d];
        float x1 = so[r * 132 + d];
        float x2 = so[r * 132 + d + 64];
        float v0 = (x1 * cs - x2 * sn) * scale;
        float v1 = (x2 * cs + x1 * sn) * scale;
        size_t idx = ((size_t)token * nheads + head) * DHc;
        __nv_bfloat16 h0 = __float2bfloat16(v0);
        __nv_bfloat16 h1 = __float2bfloat16(v1);
        oh[idx + d]      = h0;
        ol[idx + d]      = __float2bfloat16(v0 - __bfloat162float(h0));
        oh[idx + d + 64] = h1;
        ol[idx + d + 64] = __float2bfloat16(v1 - __bfloat162float(h1));
    }
}

// ---------------- generic bf16x3 GEMM (O / G+U / D) ----------------
__global__ __launch_bounds__(256, 2) void gemm_bf16x3(
    const __nv_bfloat16* __restrict__ Ahi, const __nv_bfloat16* __restrict__ Alo,
    const __nv_bfloat16* __restrict__ Bhi1, const __nv_bfloat16* __restrict__ Blo1,
    const float* __restrict__ resid1, float* __restrict__ C1,
    const __nv_bfloat16* __restrict__ Bhi2, const __nv_bfloat16* __restrict__ Blo2,
    const float* __restrict__ resid2, float* __restrict__ C2,
    int M, int N, int K) {
    extern __shared__ uint8_t smraw[];
    const int tid = threadIdx.x;
    const int bm = blockIdx.y * 128, bn = blockIdx.x * 128;

    const __nv_bfloat16* Bhi = Bhi1; const __nv_bfloat16* Blo = Blo1;
    const float* resid = resid1;
    float* C = C1;
    if (blockIdx.z == 1) { Bhi = Bhi2; Blo = Blo2; resid = resid2; C = C2; }

    float acc[2][8][4];
    #pragma unroll
    for (int mt = 0; mt < 2; mt++)
        #pragma unroll
        for (int nt = 0; nt < 8; nt++)
            #pragma unroll
            for (int r = 0; r < 4; r++) acc[mt][nt][r] = 0.f;

    GemmCtx cx;
    gemm_setup(cx, smraw, tid, Ahi, Alo, Bhi, Blo, bm, bn, K);
    gemm_mainloop(cx, acc, K);

    const int lane = tid & 31;
    const int grp = lane >> 2, qd = lane & 3;
    #pragma unroll
    for (int mt = 0; mt < 2; mt++) {
        int row0 = bm + cx.m0 + mt * 16 + grp;
        int row1 = row0 + 8;
        #pragma unroll
        for (int nt = 0; nt < 8; nt++) {
            int lc0 = cx.n0 + nt * 8 + 2 * qd;
            int col0 = bn + lc0, col1 = col0 + 1;
            float o00 = acc[mt][nt][0], o01 = acc[mt][nt][1];
            float o10 = acc[mt][nt][2], o11 = acc[mt][nt][3];
            if (resid) {
                o00 += resid[(size_t)row0 * N + col0];
                o01 += resid[(size_t)row0 * N + col1];
                o10 += resid[(size_t)row1 * N + col0];
                o11 += resid[(size_t)row1 * N + col1];
            }
            *(float2*)(C + (size_t)row0 * N + col0) = make_float2(o00, o01);
            *(float2*)(C + (size_t)row1 * N + col0) = make_float2(o10, o11);
        }
    }
}

// ---------------- attention scores on tensor cores: S = Qs * K^T (bf16x3) ----------------
__global__ __launch_bounds__(256, 2) void attn_scores_mma(
    const __nv_bfloat16* __restrict__ qh, const __nv_bfloat16* __restrict__ ql,
    const __nv_bfloat16* __restrict__ kh, const __nv_bfloat16* __restrict__ kl,
    float* __restrict__ scores) {
    if (blockIdx.x > blockIdx.y) return;
    extern __shared__ uint8_t smraw[];
    const int tid = threadIdx.x;
    const int bh = blockIdx.z;
    const int b = bh >> 4, hd = bh & 15, kvh = hd >> 2;
    const int bm = blockIdx.y * 128, bn = blockIdx.x * 128;
    float* C = scores + (size_t)bh * Sc * Sc;

    float acc[2][8][4];
    #pragma unroll
    for (int mt = 0; mt < 2; mt++)
        #pragma unroll
        for (int nt = 0; nt < 8; nt++)
            #pragma unroll
            for (int r = 0; r < 4; r++) acc[mt][nt][r] = 0.f;

    GemmCtx cx;
    {
        const int warpId = tid >> 5, lane = tid & 31;
        cx.m0 = (warpId & 3) * 32;
        cx.n0 = (warpId >> 2) * 64;
        cx.lrow16 = lane & 15;
        cx.lch = lane >> 4;
        cx.lsw = (cx.lrow16 >> 1) & 3;
        cx.sb = sptr(smraw);
        int lrow = tid >> 1;
        cx.lg0 = (tid & 1) * 2;
        cx.lswz = (lrow >> 1) & 3;
        cx.pAh = qh + (size_t)b * Sc * QNc + (size_t)hd * DHc + (size_t)(bm + lrow) * QNc;
        cx.pAl = ql + (size_t)b * Sc * QNc + (size_t)hd * DHc + (size_t)(bm + lrow) * QNc;
        cx.pBh = kh + (size_t)b * Sc * KNc + (size_t)kvh * DHc + (size_t)(bn + lrow) * KNc;
        cx.pBl = kl + (size_t)b * Sc * KNc + (size_t)kvh * DHc + (size_t)(bn + lrow) * KNc;
        cx.srow = cx.sb + lrow * 64;
    }
    gemm_mainloop(cx, acc, DHc);

    const int lane = tid & 31;
    const int grp = lane >> 2, qd = lane & 3;
    #pragma unroll
    for (int mt = 0; mt < 2; mt++) {
        int row0 = bm + cx.m0 + mt * 16 + grp;
        int row1 = row0 + 8;
        #pragma unroll
        for (int nt = 0; nt < 8; nt++) {
            int col = bn + cx.n0 + nt * 8 + 2 * qd;
            *(float2*)(C + (size_t)row0 * Sc + col) = make_float2(acc[mt][nt][0], acc[mt][nt][1]);
            *(float2*)(C + (size_t)row1 * Sc + col) = make_float2(acc[mt][nt][2], acc[mt][nt][3]);
        }
    }
}

// ---------------- attention context on tensor cores: ctx = P * V (bf16x3) ----------------
__global__ __launch_bounds__(256, 2) void attn_ctx_mma(
    const __nv_bfloat16* __restrict__ ph, const __nv_bfloat16* __restrict__ pl,
    const __nv_bfloat16* __restrict__ vTh, const __nv_bfloat16* __restrict__ vTl,
    __nv_bfloat16* __restrict__ ch, __nv_bfloat16* __restrict__ cl) {
    extern __shared__ uint8_t smraw[];
    const int tid = threadIdx.x;
    const int bh = blockIdx.z;
    const int b = bh >> 4, hd = bh & 15, kvh = hd >> 2;
    const int bm = blockIdx.y * 128;

    float acc[2][8][4];
    #pragma unroll
    for (int mt = 0; mt < 2; mt++)
        #pragma unroll
        for (int nt = 0; nt < 8; nt++)
            #pragma unroll
            for (int r = 0; r < 4; r++) acc[mt][nt][r] = 0.f;

    GemmCtx cx;
    {
        const int warpId = tid >> 5, lane = tid & 31;
        cx.m0 = (warpId & 3) * 32;
        cx.n0 = (warpId >> 2) * 64;
        cx.lrow16 = lane & 15;
        cx.lch = lane >> 4;
        cx.lsw = (cx.lrow16 >> 1) & 3;
        cx.sb = sptr(smraw);
        int lrow = tid >> 1;
        cx.lg0 = (tid & 1) * 2;
        cx.lswz = (lrow >> 1) & 3;
        cx.pAh = ph + (size_t)bh * Sc * Sc + (size_t)(bm + lrow) * Sc;
        cx.pAl = pl + (size_t)bh * Sc * Sc + (size_t)(bm + lrow) * Sc;
        cx.pBh = vTh + ((size_t)b * KNc + (size_t)kvh * DHc + lrow) * Sc;
        cx.pBl = vTl + ((size_t)b * KNc + (size_t)kvh * DHc + lrow) * Sc;
        cx.srow = cx.sb + lrow * 64;
    }
    gemm_mainloop(cx, acc, ((bm >> 5) + 4) << 5);   // causal truncation (exact)

    const int lane = tid & 31;
    const int grp = lane >> 2, qd = lane & 3;
    #pragma unroll
    for (int mt = 0; mt < 2; mt++) {
        int lr0 = cx.m0 + mt * 16 + grp;
        #pragma unroll
        for (int half = 0; half < 2; half++) {
            int row = bm + lr0 + half * 8;
            size_t base = ((size_t)(b * Sc + row)) * QNc + (size_t)hd * DHc;
            #pragma unroll
            for (int nt = 0; nt < 8; nt++) {
                int col = cx.n0 + nt * 8 + 2 * qd;
                float v0 = acc[mt][nt][half * 2 + 0];
                float v1 = acc[mt][nt][half * 2 + 1];
                __nv_bfloat16 h0 = __float2bfloat16(v0);
                __nv_bfloat16 h1 = __float2bfloat16(v1);
                __nv_bfloat162 hv; hv.x = h0; hv.y = h1;
                __nv_bfloat162 lv;
                lv.x = __float2bfloat16(v0 - __bfloat162float(h0));
                lv.y = __float2bfloat16(v1 - __bfloat162float(h1));
                *(__nv_bfloat162*)(ch + base + col) = hv;
                *(__nv_bfloat162*)(cl + base + col) = lv;
            }
        }
    }
}

// ---------------- V transpose + split ----------------
__global__ void vsplitT_kernel(const float* __restrict__ v,
                               __nv_bfloat16* __restrict__ vTh,
                               __nv_bfloat16* __restrict__ vTl) {
    __shared__ float tile[32][33];
    int b = blockIdx.z;
    int t0 = blockIdx.x * 32, d0 = blockIdx.y * 32;
    int tx = threadIdx.x, ty = threadIdx.y;
    for (int i = ty; i < 32; i += 8)
        tile[i][tx] = v[(size_t)(b * Sc + t0 + i) * KNc + d0 + tx];
    __syncthreads();
    for (int i = ty; i < 32; i += 8) {
        float val = tile[tx][i];
        size_t idx = ((size_t)b * KNc + d0 + i) * Sc + t0 + tx;
        __nv_bfloat16 hb = __float2bfloat16(val);
        vTh[idx] = hb;
        vTl[idx] = __float2bfloat16(val - __bfloat162float(hb));
    }
}

// ---------------- masked softmax -> bf16 hi/lo P ----------------
__global__ void softmax_kernel(const float* __restrict__ scores, const int* __restrict__ mask,
                               __nv_bfloat16* __restrict__ ph, __nv_bfloat16* __restrict__ pl) {
    int row = blockIdx.x;
    int qpos = row % Sc;
    int b = row / (NHc * Sc);
    const float* r = scores + (size_t)row * Sc;
    int t = threadIdx.x;
    float v[4];
    float mx = -3.0e38f;
    #pragma unroll
    for (int i = 0; i < 4; i++) {
        int k = t + 128 * i;
        bool ok = (k <= qpos) && (mask[b * Sc + k] > 0);
        v[i] = ok ? r[k] : -1e30f;
        mx = fmaxf(mx, v[i]);
    }
    __shared__ float sh[128];
    sh[t] = mx; __syncthreads();
    for (int o = 64; o; o >>= 1) { if (t < o) sh[t] = fmaxf(sh[t], sh[t + o]); __syncthreads(); }
    mx = sh[0]; __syncthreads();
    float sm = 0.f;
    #pragma unroll
    for (int i = 0; i < 4; i++) { v[i] = expf(v[i] - mx); sm += v[i]; }
    sh[t] = sm; __syncthreads();
    for (int o = 64; o; o >>= 1) { if (t < o) sh[t] += sh[t + o]; __syncthreads(); }
    float inv = 1.0f / sh[0];
    #pragma unroll
    for (int i = 0; i < 4; i++) {
        float p = v[i] * inv;
        __nv_bfloat16 hb = __float2bfloat16(p);
        ph[(size_t)row * Sc + t + 128 * i] = hb;
        pl[(size_t)row * Sc + t + 128 * i] = __float2bfloat16(p - __bfloat162float(hb));
    }
}

// ---------------- silu(g)*u -> bf16 hi/lo ----------------
__global__ void silu_mul_kernel(const float* __restrict__ g, const float* __restrict__ u,
                                __nv_bfloat16* __restrict__ gh, __nv_bfloat16* __restrict__ gl, int n) {
    int i = blockIdx.x * 256 + threadIdx.x;
    if (i < n) {
        float x = g[i];
        float v = (x / (1.0f + expf(-x))) * u[i];
        __nv_bfloat16 hb = __float2bfloat16(v);
        gh[i] = hb;
        gl[i] = __float2bfloat16(v - __bfloat162float(hb));
    }
}

// ---------------- final pooling + rmsnorm(lnf) ----------------
__global__ void pool_kernel(const float* __restrict__ h, const int* __restrict__ mask,
                            const float* __restrict__ lnf, float* __restrict__ pooled) {
    int b = blockIdx.x;
    int t = threadIdx.x;
    __shared__ float sh[256];
    int cnt = 0;
    for (int i = t; i < Sc; i += 256) cnt += mask[b * Sc + i];
    sh[t] = (float)cnt; __syncthreads();
    for (int o = 128; o; o >>= 1) { if (t < o) sh[t] += sh[t + o]; __syncthreads(); }
    int last = (int)sh[0] - 1;
    __syncthreads();
    const float* row = h + ((size_t)b * Sc + last) * Hc;
    float ss = 0.f;
    for (int i = t; i < Hc; i += 256) { float x = row[i]; ss += x * x; }
    sh[t] = ss; __syncthreads();
    for (int o = 128; o; o >>= 1) { if (t < o) sh[t] += sh[t + o]; __syncthreads(); }
    float sc = rsqrtf(sh[0] / (float)Hc + 1e-6f);
    for (int i = t; i < Hc; i += 256) pooled[b * Hc + i] = row[i] * sc * lnf[i];
}

// ---------------- classifier ----------------
__global__ void cls1_kernel(const float* __restrict__ pooled, const float* __restrict__ cw1,
                            const float* __restrict__ cb1, float* __restrict__ hid) {
    int n = blockIdx.x * 128 + threadIdx.x;
    int b = blockIdx.y;
    float acc = cb1[n];
    const float* p = pooled + (size_t)b * Hc;
    for (int k = 0; k < Hc; k++) acc += p[k] * cw1[(size_t)k * Hc + n];
    hid[(size_t)b * Hc + n] = fmaxf(acc, 0.f);
}

__global__ void cls2_kernel(const float* __restrict__ hid, const float* __restrict__ cw2,
                            const float* __restrict__ cb2, float* __restrict__ out) {
    int b = blockIdx.x >> 1, c = blockIdx.x & 1;
    float acc = 0.f;
    for (int k = threadIdx.x; k < Hc; k += 128) acc += hid[(size_t)b * Hc + k] * cw2[k * NCc + c];
    __shared__ float sh[128];
    sh[threadIdx.x] = acc; __syncthreads();
    for (int o = 64; o; o >>= 1) { if (threadIdx.x < o) sh[threadIdx.x] += sh[threadIdx.x + o]; __syncthreads(); }
    if (threadIdx.x == 0) out[b * NCc + c] = sh[0] + cb2[c];
}

// ---------------- host orchestration ----------------
extern "C" void kernel_launch(void* const* d_in, const int* in_sizes, int n_in,
                              void* d_out, int out_size) {
    (void)in_sizes; (void)n_in; (void)out_size;
    const int*   ids   = (const int*)d_in[0];
    const int*   mask  = (const int*)d_in[1];
    const float* embed = (const float*)d_in[2];
    const float* ln1   = (const float*)d_in[3];
    const float* wq    = (const float*)d_in[4];
    const float* bq    = (const float*)d_in[5];
    const float* wk    = (const float*)d_in[6];
    const float* bk    = (const float*)d_in[7];
    const float* wv    = (const float*)d_in[8];
    const float* bv    = (const float*)d_in[9];
    const float* wo    = (const float*)d_in[10];
    const float* laq   = (const float*)d_in[11];
    const float* lbq   = (const float*)d_in[12];
    const float* lak   = (const float*)d_in[13];
    const float* lbk   = (const float*)d_in[14];
    const float* lav   = (const float*)d_in[15];
    const float* lbv   = (const float*)d_in[16];
    const float* lao   = (const float*)d_in[17];
    const float* lbo   = (const float*)d_in[18];
    const float* ln2   = (const float*)d_in[19];
    const float* wg    = (const float*)d_in[20];
    const float* wu    = (const float*)d_in[21];
    const float* wd    = (const float*)d_in[22];
    const float* lnf   = (const float*)d_in[23];
    const float* cw1   = (const float*)d_in[24];
    const float* cb1   = (const float*)d_in[25];
    const float* cw2   = (const float*)d_in[26];
    const float* cb2   = (const float*)d_in[27];
    float* out = (float*)d_out;

    cudaFuncSetAttribute(gemm_qkv, cudaFuncAttributeMaxDynamicSharedMemorySize, GEMM_SMEM);
    cudaFuncSetAttribute(gemm_bf16x3, cudaFuncAttributeMaxDynamicSharedMemorySize, GEMM_SMEM);
    cudaFuncSetAttribute(attn_scores_mma, cudaFuncAttributeMaxDynamicSharedMemorySize, GEMM_SMEM);
    cudaFuncSetAttribute(attn_ctx_mma, cudaFuncAttributeMaxDynamicSharedMemorySize, GEMM_SMEM);

    float *h, *v, *sc, *g, *u, *pooled, *cls, *rc, *rs;
    __nv_bfloat16 *xh, *xl, *qh, *ql, *kh, *kl, *vTh, *vTl, *ph, *pl, *ch, *cl, *gh, *gl, *whT, *wlT;
    cudaGetSymbolAddress((void**)&h,   d_h);
    cudaGetSymbolAddress((void**)&xh,  d_xh);
    cudaGetSymbolAddress((void**)&xl,  d_xl);
    cudaGetSymbolAddress((void**)&v,   d_v);
    cudaGetSymbolAddress((void**)&qh,  d_qh);
    cudaGetSymbolAddress((void**)&ql,  d_ql);
    cudaGetSymbolAddress((void**)&kh,  d_kh);
    cudaGetSymbolAddress((void**)&kl,  d_kl);
    cudaGetSymbolAddress((void**)&vTh, d_vTh);
    cudaGetSymbolAddress((void**)&vTl, d_vTl);
    cudaGetSymbolAddress((void**)&rc,  d_ropec);
    cudaGetSymbolAddress((void**)&rs,  d_ropes);
    cudaGetSymbolAddress((void**)&sc,  d_sc);
    cudaGetSymbolAddress((void**)&ph,  d_ph);
    cudaGetSymbolAddress((void**)&pl,  d_pl);
    cudaGetSymbolAddress((void**)&ch,  d_ch);
    cudaGetSymbolAddress((void**)&cl,  d_cl);
    cudaGetSymbolAddress((void**)&g,   d_g);
    cudaGetSymbolAddress((void**)&u,   d_u);
    cudaGetSymbolAddress((void**)&gh,  d_gh);
    cudaGetSymbolAddress((void**)&gl,  d_gl);
    cudaGetSymbolAddress((void**)&pooled, d_pooled);
    cudaGetSymbolAddress((void**)&cls,    d_cls);
    cudaGetSymbolAddress((void**)&whT,    d_whT);
    cudaGetSymbolAddress((void**)&wlT,    d_wlT);

    wsplit_all_kernel<<<Lc * TILES_PER_LAYER, dim3(32, 8)>>>(
        wq, wk, wv, wo, wg, wu, wd,
        laq, lbq, lak, lbk, lav, lbv, lao, lbo, whT, wlT);
    rope_table_kernel<<<Sc, 64>>>(rc, rs);
    embed_kernel<<<MTc, 256>>>(ids, embed, h);

    for (int l = 0; l < Lc; l++) {
        size_t lw = (size_t)l * LAYER_W;
        const float* LN1 = ln1 + (size_t)l * Hc;
        const float* BQ = bq + (size_t)l * QNc;
        const float* BK = bk + (size_t)l * KNc;
        const float* BV = bv + (size_t)l * KNc;
        const float* LN2 = ln2 + (size_t)l * Hc;

        rmsnorm_kernel<<<MTc, 256>>>(h, LN1, xh, xl);

        // fused QKV projection + RoPE epilogue: 24 N-tiles x 16 M-tiles = 384 CTAs
        gemm_qkv<<<dim3(24, MTc / 128), 256, GEMM_SMEM>>>(
            xh, xl,
            whT + lw + WOFF_Q, wlT + lw + WOFF_Q,
            whT + lw + WOFF_K, wlT + lw + WOFF_K,
            whT + lw + WOFF_V, wlT + lw + WOFF_V,
            BQ, BK, BV, rc, rs, qh, ql, kh, kl, v);

        vsplitT_kernel<<<dim3(16, 16, Bc), dim3(32, 8)>>>(v, vTh, vTl);

        attn_scores_mma<<<dim3(4, 4, Bc * NHc), 256, GEMM_SMEM>>>(qh, ql, kh, kl, sc);
        softmax_kernel<<<Bc * NHc * Sc, 128>>>(sc, mask, ph, pl);
        attn_ctx_mma<<<dim3(1, 4, Bc * NHc), 256, GEMM_SMEM>>>(ph, pl, vTh, vTl, ch, cl);

        gemm_bf16x3<<<dim3(Hc / 128, MTc / 128, 1), 256, GEMM_SMEM>>>(
            ch, cl,
            whT + lw + WOFF_O, wlT + lw + WOFF_O, h, h,
            nullptr, nullptr, nullptr, nullptr,
            MTc, Hc, QNc);

        rmsnorm_kernel<<<MTc, 256>>>(h, LN2, xh, xl);
        gemm_bf16x3<<<dim3(Fc / 128, MTc / 128, 2), 256, GEMM_SMEM>>>(
            xh, xl,
            whT + lw + WOFF_G, wlT + lw + WOFF_G, nullptr, g,
            whT + lw + WOFF_U, wlT + lw + WOFF_U, nullptr, u,
            MTc, Fc, Hc);
        silu_mul_kernel<<<(MTc * Fc) / 256, 256>>>(g, u, gh, gl, MTc * Fc);
        gemm_bf16x3<<<dim3(Hc / 128, MTc / 128, 1), 256, GEMM_SMEM>>>(
            gh, gl,
            whT + lw + WOFF_D, wlT + lw + WOFF_D, h, h,
            nullptr, nullptr, nullptr, nullptr,
            MTc, Hc, Fc);
    }

    pool_kernel<<<Bc, 256>>>(h, mask, lnf, pooled);
    cls1_kernel<<<dim3(Hc / 128, Bc), 128>>>(pooled, cw1, cb1, cls);
    cls2_kernel<<<Bc * NCc, 128>>>(cls, cw2, cb2, out);
}